// round 13
// baseline (speedup 1.0000x reference)
#include <cuda_runtime.h>
#include <cuda_fp16.h>
#include <math.h>
#include <stdint.h>

#define H_DIM 4096
#define QKVW  6144          // (NH + 2*NKV) * D
#define NHq   32
#define NKVq  8
#define Dh    128
#define Sq    2048
#define Bq    2
#define Mrows 4096          // B * S
#define GK    4096          // K dim of both big GEMMs
#define NKCH  (GK / 64)     // 64 k-chunks per tile row

// GEMM pipeline: 3 stages x 32KB = 96KB -> 2 CTAs/SM
#define NSTG 3
#define STAGE_BYTES 32768
#define NIT  (GK / 64)

// attention smem layout (bytes) — K/V double buffered
#define SM_QH 0
#define SM_QL 16384
#define SM_K  32768
#define SM_VT 98304
#define SM_PH 163840
#define SM_PL 172032
#define SM_SS 180224
#define SM_MS 197120
#define SM_LS 197376
#define SM_CS 197632
#define ATTN_SMEM 197888

// scratch (device globals: allocation-guard compliant)
__device__ float  g_qkv[(size_t)Mrows * QKVW];
__device__ __half g_att[(size_t)Mrows * (NHq * Dh)];    // frag-order A tiles for GEMM2
__device__ __half g_hsr[(size_t)Mrows * H_DIM];         // frag-order A tiles for GEMM1
__device__ __half g_wqkvT[(size_t)QKVW * H_DIM];        // frag-order B tiles
__device__ __half g_woT[(size_t)H_DIM * H_DIM];         // frag-order B tiles
// attention operands (hi/lo fp16 split)
__device__ __half g_qh[(size_t)Mrows * (NHq * Dh)];
__device__ __half g_ql[(size_t)Mrows * (NHq * Dh)];
__device__ __half g_kh[(size_t)Mrows * (NKVq * Dh)];
__device__ __half g_kl[(size_t)Mrows * (NKVq * Dh)];
__device__ __half g_vth[(size_t)Mrows * (NKVq * Dh)];   // [b][kvh][d][s]
__device__ __half g_vtl[(size_t)Mrows * (NKVq * Dh)];

// ===========================================================================
// helpers (sm_80-era PTX only)
// ===========================================================================
__device__ __forceinline__ uint32_t smem_u32(const void* p) {
    uint32_t a;
    asm("{ .reg .u64 t; cvta.to.shared.u64 t, %1; cvt.u32.u64 %0, t; }" : "=r"(a) : "l"(p));
    return a;
}
__device__ __forceinline__ uint32_t lds32(uint32_t a) {
    uint32_t v; asm volatile("ld.shared.b32 %0, [%1];" : "=r"(v) : "r"(a)); return v;
}
__device__ __forceinline__ void lds64v(uint32_t* r, uint32_t a) {
    asm volatile("ld.shared.v2.b32 {%0,%1}, [%2];" : "=r"(r[0]), "=r"(r[1]) : "r"(a));
}
__device__ __forceinline__ void lds128v(uint32_t* r, uint32_t a) {
    asm volatile("ld.shared.v4.b32 {%0,%1,%2,%3}, [%4];"
                 : "=r"(r[0]), "=r"(r[1]), "=r"(r[2]), "=r"(r[3]) : "r"(a));
}
__device__ __forceinline__ void sts128(uint32_t a, uint4 v) {
    asm volatile("st.shared.v4.b32 [%0], {%1,%2,%3,%4};"
                 :: "r"(a), "r"(v.x), "r"(v.y), "r"(v.z), "r"(v.w) : "memory");
}
#define CP16(smaddr, gptr) \
    asm volatile("cp.async.cg.shared.global [%0], [%1], 16;" :: "r"(smaddr), "l"(gptr) : "memory")
#define CP_COMMIT() asm volatile("cp.async.commit_group;" ::: "memory")
#define CP_WAIT(n)  asm volatile("cp.async.wait_group %0;" :: "n"(n) : "memory")

// fp16 m16n8k16 MMA, fp32 accumulate
__device__ __forceinline__ void mma_f16(float* d, const uint32_t* a, const uint32_t* b) {
    asm volatile("mma.sync.aligned.m16n8k16.row.col.f32.f16.f16.f32 "
                 "{%0,%1,%2,%3}, {%4,%5,%6,%7}, {%8,%9}, {%0,%1,%2,%3};"
                 : "+f"(d[0]), "+f"(d[1]), "+f"(d[2]), "+f"(d[3])
                 : "r"(a[0]), "r"(a[1]), "r"(a[2]), "r"(a[3]), "r"(b[0]), "r"(b[1]));
}

// ===========================================================================
// Fragment-order tile layouts:
// A tile (128 rows x 64 halves = 16KB): byte(row, word c) =
//   (row>>6)*8192 + (c>>3)*2048 + ((row&63)>>4)*512 + (row&7)*64
//   + (c&3)*16 + ((c&7)>>2)*8 + (((row>>3)&1))*4
//   -> lds128 at wm*8192 + ks*2048 + i*512 + lane*16 yields {a0,a1,a2,a3}.
// B tile (128 cols x 64 halves = 16KB): byte(col, c) =
//   (col>>5)*4096 + (c>>3)*1024 + ((col>>3)&3)*256 + (col&7)*32
//   + (c&3)*8 + ((c&7)>>2)*4
//   -> lds64 at wn*4096 + ks*1024 + j*256 + lane*8 yields {b0,b1}.
// ===========================================================================

// fp16 mma.sync GEMM, frag-order operands: C = A_tiles * B_tiles^T (fp32 out)
__global__ __launch_bounds__(256, 2) void mma_gemm(const __half* __restrict__ A,
                                                   const __half* __restrict__ BT,
                                                   float* __restrict__ C, int Ntot) {
    extern __shared__ char smraw[];
    const uint32_t SB = smem_u32(smraw);

    int tid  = threadIdx.x;
    int lane = tid & 31, wid = tid >> 5;
    int wm = wid & 1, wn = wid >> 1;
    int g  = lane >> 2, q = lane & 3;

    // tile swizzle: groups of 8 N-tiles across all M-tiles (L2 locality)
    int l = blockIdx.y * gridDim.x + blockIdx.x;
    int per = gridDim.y << 3;
    int gq = l / per, rr = l - gq * per;
    int ntile = (gq << 3) + (rr & 7);
    int mtile = rr >> 3;

    const char* gaT = (const char*)A  + (size_t)mtile * NKCH * 16384;
    const char* gbT = (const char*)BT + (size_t)ntile * NKCH * 16384;

    float acc[4][4][4] = {};

    // prologue: linear 16KB+16KB copies
#pragma unroll
    for (int p = 0; p < NSTG - 1; p++) {
        uint32_t as = SB + p * STAGE_BYTES;
#pragma unroll
        for (int cc = 0; cc < 4; cc++) {
            CP16(as + tid * 64 + cc * 16,         gaT + (size_t)p * 16384 + tid * 64 + cc * 16);
            CP16(as + 16384 + tid * 64 + cc * 16, gbT + (size_t)p * 16384 + tid * 64 + cc * 16);
        }
        CP_COMMIT();
    }

    uint32_t aBase = (uint32_t)(wm * 8192) + lane * 16;
    uint32_t bBase = 16384u + (uint32_t)(wn * 4096) + lane * 8;

    int scur = 0, spf = NSTG - 1;
    for (int it = 0; it < NIT; it++) {
        CP_WAIT(NSTG - 2);
        __syncthreads();

        int pf = it + NSTG - 1;
        if (pf < NIT) {
            uint32_t as = SB + spf * STAGE_BYTES;
#pragma unroll
            for (int cc = 0; cc < 4; cc++) {
                CP16(as + tid * 64 + cc * 16,         gaT + (size_t)pf * 16384 + tid * 64 + cc * 16);
                CP16(as + 16384 + tid * 64 + cc * 16, gbT + (size_t)pf * 16384 + tid * 64 + cc * 16);
            }
        }
        CP_COMMIT();

        uint32_t stage = SB + scur * STAGE_BYTES;
#pragma unroll
        for (int ks = 0; ks < 4; ks++) {
            uint32_t afr[4][4], bfr[4][2];
#pragma unroll
            for (int i = 0; i < 4; i++)
                lds128v(afr[i], stage + aBase + ks * 2048 + i * 512);
#pragma unroll
            for (int j = 0; j < 4; j++)
                lds64v(bfr[j], stage + bBase + ks * 1024 + j * 256);
#pragma unroll
            for (int i = 0; i < 4; i++)
#pragma unroll
                for (int j = 0; j < 4; j++)
                    mma_f16(acc[i][j], afr[i], bfr[j]);
        }

        if (++scur == NSTG) scur = 0;
        if (++spf == NSTG) spf = 0;
    }

    float* Cp = C + (size_t)(mtile * 128 + wm * 64 + g) * Ntot + ntile * 128 + wn * 32 + q * 2;
#pragma unroll
    for (int i = 0; i < 4; i++)
#pragma unroll
        for (int j = 0; j < 4; j++) {
            *(float2*)(Cp + (size_t)(i * 16) * Ntot + j * 8)     = make_float2(acc[i][j][0], acc[i][j][1]);
            *(float2*)(Cp + (size_t)(i * 16 + 8) * Ntot + j * 8) = make_float2(acc[i][j][2], acc[i][j][3]);
        }
}

// ===========================================================================
// prep: A operand (hs fp32 row-major) -> frag-order fp16 tiles
// grid (NKCH, M/128), 256 threads. 2 threads/row, 16 words each.
// ===========================================================================
__global__ void prep_a_frag(const float* __restrict__ in, __half* __restrict__ out) {
    __shared__ uint32_t frag[4096];   // 16KB
    int kchunk = blockIdx.x, mtile = blockIdx.y;
    int tid = threadIdx.x;
    int r  = tid >> 1;                // row in tile 0..127
    int c0 = (tid & 1) * 16;          // word offset 0/16

    const float* src = in + ((size_t)(mtile * 128 + r)) * GK + kchunk * 64 + c0 * 2;
    int wmHalf = r >> 6, gr = r & 63;
    uint32_t rowbase = (uint32_t)(wmHalf * 8192 + (gr >> 4) * 512 + ((gr >> 3) & 1) * 4
                                  + (gr & 7) * 64);
#pragma unroll
    for (int i4 = 0; i4 < 16; i4++) {     // FIXED: 16 words per thread
        float2 v = *(const float2*)(src + i4 * 2);
        __half2 hv = __floats2half2_rn(v.x, v.y);
        int c = c0 + i4;
        int w = c & 7, ks = c >> 3, qq = w & 3, hi = w >> 2;
        frag[(rowbase + ks * 2048 + qq * 16 + hi * 8) >> 2] = *(uint32_t*)&hv;
    }
    __syncthreads();
    uint4* dst = (uint4*)(out + ((size_t)(mtile * NKCH + kchunk)) * 8192);
    const uint4* s4 = (const uint4*)frag;
#pragma unroll
    for (int i = 0; i < 4; i++) dst[tid + i * 256] = s4[tid + i * 256];
}

// ===========================================================================
// prep: B operand (w fp32 [K][N] row-major) -> frag-order fp16 tiles [ntile][kchunk]
// grid (NKCH, N/128), 256 threads.
// ===========================================================================
__global__ void prep_b_frag(const float* __restrict__ in, __half* __restrict__ out, int N) {
    __shared__ __half t[64][136];
    __shared__ uint32_t frag[4096];
    int kchunk = blockIdx.x, ntile = blockIdx.y;
    int tid = threadIdx.x;
    int k0 = kchunk * 64, n0 = ntile * 128;

    // load + convert: coalesced along n
    {
        int nn = (tid & 31) * 4;
        int kk0 = tid >> 5;
#pragma unroll
        for (int kk = 0; kk < 64; kk += 8) {
            float4 v = *(const float4*)(in + (size_t)(k0 + kk + kk0) * N + n0 + nn);
            t[kk + kk0][nn]     = __float2half_rn(v.x);
            t[kk + kk0][nn + 1] = __float2half_rn(v.y);
            t[kk + kk0][nn + 2] = __float2half_rn(v.z);
            t[kk + kk0][nn + 3] = __float2half_rn(v.w);
        }
    }
    __syncthreads();

    // build frag tile
    {
        int col = tid >> 1;
        int c0  = (tid & 1) * 16;
        uint32_t colbase = (uint32_t)((col >> 5) * 4096 + ((col >> 3) & 3) * 256
                                      + (col & 7) * 32);
#pragma unroll
        for (int i = 0; i < 16; i++) {
            int c = c0 + i;
            int w = c & 7, ks = c >> 3, qq = w & 3, hi = w >> 2;
            __half2 hv = __halves2half2(t[c * 2][col], t[c * 2 + 1][col]);
            frag[(colbase + ks * 1024 + qq * 8 + hi * 4) >> 2] = *(uint32_t*)&hv;
        }
    }
    __syncthreads();
    uint4* dst = (uint4*)(out + ((size_t)(ntile * NKCH + kchunk)) * 8192);
    const uint4* s4 = (const uint4*)frag;
#pragma unroll
    for (int i = 0; i < 4; i++) dst[tid + i * 256] = s4[tid + i * 256];
}

// ===========================================================================
// fused RoPE + q/k split, v transpose split (R11-proven)
// ===========================================================================
__global__ void prep_q(const float* __restrict__ qkv,
                       __half* __restrict__ qh, __half* __restrict__ ql) {
    const float scale = 0.08838834764831845f;
    int t = blockIdx.x * blockDim.x + threadIdx.x;
    if (t >= Mrows * (NHq * Dh / 4)) return;
    int m = t / 1024;
    int cc = (t % 1024) * 4;
    int h = cc >> 7, d = cc & 127;
    int b = m >> 11, s = m & 2047;
    float4 v = *(const float4*)(qkv + (size_t)m * QKVW + cc);
    float f[4];
    {
        int p0 = d >> 1;
        float i0 = exp2f(-(float)p0 * (13.287712379549449f / 64.0f));
        float i1 = exp2f(-(float)(p0 + 1) * (13.287712379549449f / 64.0f));
        float sn0, cs0, sn1, cs1;
        sincosf((float)s * i0, &sn0, &cs0);
        sincosf((float)s * i1, &sn1, &cs1);
        f[0] = (v.x * cs0 - v.y * sn0) * scale;
        f[1] = (v.y * cs0 + v.x * sn0) * scale;
        f[2] = (v.z * cs1 - v.w * sn1) * scale;
        f[3] = (v.w * cs1 + v.z * sn1) * scale;
    }
    size_t o = ((size_t)((b * NHq + h) * Sq + s)) * Dh + d;
    __half hh[4], hl[4];
#pragma unroll
    for (int i = 0; i < 4; i++) {
        hh[i] = __float2half_rn(f[i]);
        hl[i] = __float2half_rn(f[i] - __half2float(hh[i]));
    }
    *(uint2*)(qh + o) = *(uint2*)hh;
    *(uint2*)(ql + o) = *(uint2*)hl;
}

__global__ void prep_k(const float* __restrict__ qkv,
                       __half* __restrict__ kh, __half* __restrict__ kl) {
    int t = blockIdx.x * blockDim.x + threadIdx.x;
    if (t >= Mrows * (NKVq * Dh / 4)) return;
    int m = t / 256;
    int cc = (t % 256) * 4;
    int kvh = cc >> 7, d = cc & 127;
    int b = m >> 11, s = m & 2047;
    float4 v = *(const float4*)(qkv + (size_t)m * QKVW + NHq * Dh + cc);
    float f[4];
    {
        int p0 = d >> 1;
        float i0 = exp2f(-(float)p0 * (13.287712379549449f / 64.0f));
        float i1 = exp2f(-(float)(p0 + 1) * (13.287712379549449f / 64.0f));
        float sn0, cs0, sn1, cs1;
        sincosf((float)s * i0, &sn0, &cs0);
        sincosf((float)s * i1, &sn1, &cs1);
        f[0] = v.x * cs0 - v.y * sn0;
        f[1] = v.y * cs0 + v.x * sn0;
        f[2] = v.z * cs1 - v.w * sn1;
        f[3] = v.w * cs1 + v.z * sn1;
    }
    size_t o = ((size_t)((b * NKVq + kvh) * Sq + s)) * Dh + d;
    __half hh[4], hl[4];
#pragma unroll
    for (int i = 0; i < 4; i++) {
        hh[i] = __float2half_rn(f[i]);
        hl[i] = __float2half_rn(f[i] - __half2float(hh[i]));
    }
    *(uint2*)(kh + o) = *(uint2*)hh;
    *(uint2*)(kl + o) = *(uint2*)hl;
}

__global__ void prep_vt(const float* __restrict__ qkv,
                        __half* __restrict__ vth, __half* __restrict__ vtl) {
    __shared__ float t[32][33];
    int bk = blockIdx.z;
    int b = bk >> 3, kvh = bk & 7;
    int x = blockIdx.x * 32 + threadIdx.x;   // d
    int y0 = blockIdx.y * 32;                // s
    const float* src = qkv + (size_t)(b * Sq) * QKVW + (NHq + NKVq) * Dh + kvh * Dh;
#pragma unroll
    for (int j = threadIdx.y; j < 32; j += 8)
        t[j][threadIdx.x] = src[(size_t)(y0 + j) * QKVW + x];
    __syncthreads();
    int xo = y0 + threadIdx.x;      // s
    int yo0 = blockIdx.x * 32;      // d
#pragma unroll
    for (int j = threadIdx.y; j < 32; j += 8) {
        float v = t[threadIdx.x][j];
        int d = yo0 + j;
        size_t o = ((size_t)bk * Dh + d) * Sq + xo;
        __half hi = __float2half_rn(v);
        vth[o] = hi;
        vtl[o] = __float2half_rn(v - __half2float(hi));
    }
}

// ===========================================================================
// Causal GQA flash attention: split-fp16 MMA, K/V double-buffered cp.async.
// Epilogue writes att directly in frag-order A tiles for GEMM2.
// ===========================================================================
__global__ __launch_bounds__(256) void attn_kernel(const __half* __restrict__ qh,
                                                   const __half* __restrict__ ql,
                                                   const __half* __restrict__ kh,
                                                   const __half* __restrict__ kl,
                                                   const __half* __restrict__ vth,
                                                   const __half* __restrict__ vtl,
                                                   __half* __restrict__ att) {
    extern __shared__ char smc[];
    const uint32_t SMB = smem_u32(smc);
    float* Ss  = (float*)(smc + SM_SS);
    float* m_s = (float*)(smc + SM_MS);
    float* l_s = (float*)(smc + SM_LS);
    float* c_s = (float*)(smc + SM_CS);

    int tid  = threadIdx.x;
    int lane = tid & 31, wid = tid >> 5;
    int g = lane >> 2, q = lane & 3;
    int wm = wid & 1, wn = wid >> 1;

    int qtile = blockIdx.x;
    int bh    = blockIdx.y;
    int b     = bh >> 5;
    int h     = bh & 31;
    int kvh   = h >> 2;

    const __half* qhb = qh + ((size_t)((b * NHq + h) * Sq + qtile * 64)) * Dh;
    const __half* qlb = ql + ((size_t)((b * NHq + h) * Sq + qtile * 64)) * Dh;
    const __half* khb = kh + ((size_t)((b * NKVq + kvh) * Sq)) * Dh;
    const __half* klb = kl + ((size_t)((b * NKVq + kvh) * Sq)) * Dh;
    const __half* vthb = vth + ((size_t)(b * NKVq + kvh) * Dh) * Sq;
    const __half* vtlb = vtl + ((size_t)(b * NKVq + kvh) * Dh) * Sq;

    int krow = tid >> 2, kc0 = (tid & 3) * 4;
    int vrow = tid >> 1, vc0 = (tid & 1) * 4;

    // --- load Q tiles + KV[0]
    {
#pragma unroll
        for (int cc = 0; cc < 4; cc++) {
            int c = kc0 + cc;
            int kc = c >> 3;
            uint32_t so = (uint32_t)(((c & 7) ^ (krow & 7)) << 4);
            uint32_t dst = SMB + kc * 8192 + krow * 128 + so;
            CP16(dst + SM_QH, (const char*)(qhb + (size_t)krow * Dh + c * 8));
            CP16(dst + SM_QL, (const char*)(qlb + (size_t)krow * Dh + c * 8));
        }
        const __half* kph = khb + (size_t)krow * Dh;
        const __half* kpl = klb + (size_t)krow * Dh;
#pragma unroll
        for (int cc = 0; cc < 4; cc++) {
            int c = kc0 + cc;
            int kc = c >> 3;
            uint32_t so = (uint32_t)(((c & 7) ^ (krow & 7)) << 4);
            uint32_t dst = SMB + SM_K + kc * 8192 + krow * 128 + so;
            CP16(dst, (const char*)(kph + c * 8));
            CP16(dst + 16384, (const char*)(kpl + c * 8));
        }
        const __half* vph = vthb + (size_t)vrow * Sq;
        const __half* vpl = vtlb + (size_t)vrow * Sq;
#pragma unroll
        for (int cc = 0; cc < 4; cc++) {
            int c = vc0 + cc;
            uint32_t so = (uint32_t)((c ^ (vrow & 7)) << 4);
            uint32_t dst = SMB + SM_VT + vrow * 128 + so;
            CP16(dst, (const char*)(vph + c * 8));
            CP16(dst + 16384, (const char*)(vpl + c * 8));
        }
        CP_COMMIT();
    }
    if (tid < 64) { m_s[tid] = -1e30f; l_s[tid] = 0.0f; }

    int srow = tid >> 2, ssub = tid & 3;

    uint32_t qAoff[2], kBoff[2], pAoff[2], vBoff[4];
#pragma unroll
    for (int i = 0; i < 2; i++) {
        qAoff[i] = (uint32_t)((wm * 32 + i * 16 + g) * 128 + q * 4);
        pAoff[i] = qAoff[i];
    }
#pragma unroll
    for (int j = 0; j < 2; j++)
        kBoff[j] = (uint32_t)((wn * 16 + j * 8 + g) * 128 + q * 4);
#pragma unroll
    for (int j = 0; j < 4; j++)
        vBoff[j] = (uint32_t)((wn * 32 + j * 8 + g) * 128 + q * 4);

    float oacc[2][4][4] = {};

    for (int kt = 0; kt <= qtile; kt++) {
        __syncthreads();

        if (kt < qtile) {
            uint32_t kb = SMB + SM_K + ((kt + 1) & 1) * 32768;
            uint32_t vb = SMB + SM_VT + ((kt + 1) & 1) * 32768;
            const __half* kph = khb + (size_t)((kt + 1) * 64 + krow) * Dh;
            const __half* kpl = klb + (size_t)((kt + 1) * 64 + krow) * Dh;
#pragma unroll
            for (int cc = 0; cc < 4; cc++) {
                int c = kc0 + cc;
                int kc = c >> 3;
                uint32_t so = (uint32_t)(((c & 7) ^ (krow & 7)) << 4);
                uint32_t dst = kb + kc * 8192 + krow * 128 + so;
                CP16(dst, (const char*)(kph + c * 8));
                CP16(dst + 16384, (const char*)(kpl + c * 8));
            }
            const __half* vph = vthb + (size_t)vrow * Sq + (kt + 1) * 64;
            const __half* vpl = vtlb + (size_t)vrow * Sq + (kt + 1) * 64;
#pragma unroll
            for (int cc = 0; cc < 4; cc++) {
                int c = vc0 + cc;
                uint32_t so = (uint32_t)((c ^ (vrow & 7)) << 4);
                uint32_t dst = vb + vrow * 128 + so;
                CP16(dst, (const char*)(vph + c * 8));
                CP16(dst + 16384, (const char*)(vpl + c * 8));
            }
            CP_COMMIT();
            CP_WAIT(1);
        } else {
            CP_WAIT(0);
        }
        __syncthreads();

        uint32_t KB = SMB + SM_K + (kt & 1) * 32768;
        uint32_t VB = SMB + SM_VT + (kt & 1) * 32768;

        // --- QK^T: split fp16 MMA
        float sacc[2][2][4] = {};
#pragma unroll
        for (int kc = 0; kc < 2; kc++) {
            uint32_t qbh = SMB + SM_QH + kc * 8192, qbl = SMB + SM_QL + kc * 8192;
            uint32_t kbh = KB + kc * 8192, kbl = KB + 16384 + kc * 8192;
#pragma unroll
            for (int ks = 0; ks < 4; ks++) {
                uint32_t o0 = (uint32_t)(((2 * ks) ^ g) << 4);
                uint32_t o1 = (uint32_t)(((2 * ks + 1) ^ g) << 4);
                uint32_t aH[2][4], aL[2][4], bH[2][2], bL[2][2];
#pragma unroll
                for (int i = 0; i < 2; i++) {
                    uint32_t rh = qbh + qAoff[i], rl2 = qbl + qAoff[i];
                    aH[i][0] = lds32(rh + o0); aH[i][1] = lds32(rh + 1024 + o0);
                    aH[i][2] = lds32(rh + o1); aH[i][3] = lds32(rh + 1024 + o1);
                    aL[i][0] = lds32(rl2 + o0); aL[i][1] = lds32(rl2 + 1024 + o0);
                    aL[i][2] = lds32(rl2 + o1); aL[i][3] = lds32(rl2 + 1024 + o1);
                }
#pragma unroll
                for (int j = 0; j < 2; j++) {
                    uint32_t rh = kbh + kBoff[j], rl2 = kbl + kBoff[j];
                    bH[j][0] = lds32(rh + o0); bH[j][1] = lds32(rh + o1);
                    bL[j][0] = lds32(rl2 + o0); bL[j][1] = lds32(rl2 + o1);
                }
#pragma unroll
                for (int i = 0; i < 2; i++)
#pragma unroll
                    for (int j = 0; j < 2; j++) {
                        mma_f16(sacc[i][j], aH[i], bH[j]);
                        mma_f16(sacc[i][j], aH[i], bL[j]);
                        mma_f16(sacc[i][j], aL[i], bH[j]);
                    }
            }
        }
#pragma unroll
        for (int i = 0; i < 2; i++)
#pragma unroll
            for (int j = 0; j < 2; j++) {
                int r0 = wm * 32 + i * 16 + g;
                int cc = wn * 16 + j * 8 + 2 * q;
                *(float2*)&Ss[r0 * 66 + cc]       = make_float2(sacc[i][j][0], sacc[i][j][1]);
                *(float2*)&Ss[(r0 + 8) * 66 + cc] = make_float2(sacc[i][j][2], sacc[i][j][3]);
            }
        __syncthreads();

        // --- online softmax (4 threads/row), write P hi/lo
        {
            int limit = (kt == qtile) ? srow : 63;
            float tm = -1e30f;
            float pv_[16];
#pragma unroll
            for (int j = 0; j < 16; j++) {
                int c = ssub * 16 + j;
                float v = Ss[srow * 66 + c];
                if (c <= limit) tm = fmaxf(tm, v);
            }
            tm = fmaxf(tm, __shfl_xor_sync(0xFFFFFFFFu, tm, 1));
            tm = fmaxf(tm, __shfl_xor_sync(0xFFFFFFFFu, tm, 2));
            float mold = m_s[srow];
            float mnew = fmaxf(mold, tm);
            float sum = 0.0f;
#pragma unroll
            for (int j = 0; j < 16; j++) {
                int c = ssub * 16 + j;
                float p = (c <= limit) ? __expf(Ss[srow * 66 + c] - mnew) : 0.0f;
                pv_[j] = p;
                sum += p;
            }
#pragma unroll
            for (int c2 = 0; c2 < 2; c2++) {
                int c = ssub * 2 + c2;
                uint32_t hw[4], lw[4];
#pragma unroll
                for (int t2 = 0; t2 < 4; t2++) {
                    float a = pv_[c2 * 8 + 2 * t2], bb = pv_[c2 * 8 + 2 * t2 + 1];
                    __half ah = __float2half_rn(a), bh2 = __float2half_rn(bb);
                    __half2 hh = __halves2half2(ah, bh2);
                    hw[t2] = *(uint32_t*)&hh;
                    __half2 ll = __floats2half2_rn(a - __half2float(ah), bb - __half2float(bh2));
                    lw[t2] = *(uint32_t*)&ll;
                }
                uint32_t so = (uint32_t)((c ^ (srow & 7)) << 4);
                sts128(SMB + SM_PH + srow * 128 + so, make_uint4(hw[0], hw[1], hw[2], hw[3]));
                sts128(SMB + SM_PL + srow * 128 + so, make_uint4(lw[0], lw[1], lw[2], lw[3]));
            }
            sum += __shfl_xor_sync(0xFFFFFFFFu, sum, 1);
            sum += __shfl_xor_sync(0xFFFFFFFFu, sum, 2);
            if (ssub == 0) {
                float corr = __expf(mold - mnew);
                l_s[srow] = l_s[srow] * corr + sum;
                m_s[srow] = mnew;
                c_s[srow] = corr;
            }
        }
        __syncthreads();

        // --- O rescale, then O += P @ VT
        float cr0[2], cr1[2];
#pragma unroll
        for (int i = 0; i < 2; i++) {
            cr0[i] = c_s[wm * 32 + i * 16 + g];
            cr1[i] = c_s[wm * 32 + i * 16 + 8 + g];
        }
#pragma unroll
        for (int i = 0; i < 2; i++)
#pragma unroll
            for (int j = 0; j < 4; j++) {
                oacc[i][j][0] *= cr0[i]; oacc[i][j][1] *= cr0[i];
                oacc[i][j][2] *= cr1[i]; oacc[i][j][3] *= cr1[i];
            }

#pragma unroll
        for (int ks = 0; ks < 4; ks++) {
            uint32_t o0 = (uint32_t)(((2 * ks) ^ g) << 4);
            uint32_t o1 = (uint32_t)(((2 * ks + 1) ^ g) << 4);
            uint32_t aH[2][4], aL[2][4], bH[4][2], bL[4][2];
#pragma unroll
            for (int i = 0; i < 2; i++) {
                uint32_t rh = SMB + SM_PH + pAoff[i], rl2 = SMB + SM_PL + pAoff[i];
                aH[i][0] = lds32(rh + o0); aH[i][1] = lds32(rh + 1024 + o0);
                aH[i][2] = lds32(rh + o1); aH[i][3] = lds32(rh + 1024 + o1);
                aL[i][0] = lds32(rl2 + o0); aL[i][1] = lds32(rl2 + 1024 + o0);
                aL[i][2] = lds32(rl2 + o1); aL[i][3] = lds32(rl2 + 1024 + o1);
            }
#pragma unroll
            for (int j = 0; j < 4; j++) {
                uint32_t rh = VB + vBoff[j], rl2 = VB + 16384 + vBoff[j];
                bH[j][0] = lds32(rh + o0); bH[j][1] = lds32(rh + o1);
                bL[j][0] = lds32(rl2 + o0); bL[j][1] = lds32(rl2 + o1);
            }
#pragma unroll
            for (int i = 0; i < 2; i++)
#pragma unroll
                for (int j = 0; j < 4; j++) {
                    mma_f16(oacc[i][j], aH[i], bH[j]);
                    mma_f16(oacc[i][j], aH[i], bL[j]);
                    mma_f16(oacc[i][j], aL[i], bH[j]);
                }
        }
    }

    // --- epilogue: O / l -> frag-order A tiles for GEMM2
    {
        int mtileA = (b * Sq + qtile * 64) >> 7;
        uint32_t wmHalf = (uint32_t)(qtile & 1) * 8192;
#pragma unroll
        for (int i = 0; i < 2; i++) {
            int ra = wm * 32 + i * 16 + g;
            float la = 1.0f / l_s[ra];
            float lb = 1.0f / l_s[ra + 8];
            uint32_t iblk = (uint32_t)(wm * 2 + i) * 512;
#pragma unroll
            for (int j = 0; j < 4; j++) {
                int kchunk = 2 * h + (wn >> 1);
                int ks = (wn & 1) * 2 + (j >> 1);
                __half2 va = __floats2half2_rn(oacc[i][j][0] * la, oacc[i][j][1] * la);
                __half2 vb = __floats2half2_rn(oacc[i][j][2] * lb, oacc[i][j][3] * lb);
                char* base = (char*)att + ((size_t)mtileA * NKCH + kchunk) * 16384
                             + wmHalf + ks * 2048 + iblk + (g * 4 + q) * 16 + (j & 1) * 8;
                *(uint2*)base = make_uint2(*(uint32_t*)&va, *(uint32_t*)&vb);
            }
        }
    }
}

// ===========================================================================
extern "C" void kernel_launch(void* const* d_in, const int* in_sizes, int n_in,
                              void* d_out, int out_size) {
    const float* hs   = (const float*)d_in[0];
    const float* wqkv = (const float*)d_in[2];
    const float* wo   = (const float*)d_in[3];
    float* out = (float*)d_out;

    float* qkvp;
    __half *attp, *hsr, *wqkvT, *woT, *qhp, *qlp, *khp, *klp, *vthp, *vtlp;
    cudaGetSymbolAddress((void**)&qkvp, g_qkv);
    cudaGetSymbolAddress((void**)&attp, g_att);
    cudaGetSymbolAddress((void**)&hsr, g_hsr);
    cudaGetSymbolAddress((void**)&wqkvT, g_wqkvT);
    cudaGetSymbolAddress((void**)&woT, g_woT);
    cudaGetSymbolAddress((void**)&qhp, g_qh);
    cudaGetSymbolAddress((void**)&qlp, g_ql);
    cudaGetSymbolAddress((void**)&khp, g_kh);
    cudaGetSymbolAddress((void**)&klp, g_kl);
    cudaGetSymbolAddress((void**)&vthp, g_vth);
    cudaGetSymbolAddress((void**)&vtlp, g_vtl);

    const int GEMM_SMEM = NSTG * STAGE_BYTES;   // 96 KB
    cudaFuncSetAttribute((const void*)mma_gemm,
                         cudaFuncAttributeMaxDynamicSharedMemorySize, GEMM_SMEM);
    cudaFuncSetAttribute((const void*)attn_kernel,
                         cudaFuncAttributeMaxDynamicSharedMemorySize, ATTN_SMEM);

    // 0) operand prep: frag-order tiles
    prep_a_frag<<<dim3(NKCH, Mrows / 128), 256>>>(hs, hsr);
    prep_b_frag<<<dim3(NKCH, QKVW / 128), 256>>>(wqkv, wqkvT, QKVW);
    prep_b_frag<<<dim3(NKCH, H_DIM / 128), 256>>>(wo, woT, H_DIM);

    // 1) QKV GEMM
    mma_gemm<<<dim3(QKVW / 128, Mrows / 128), 256, GEMM_SMEM>>>(hsr, wqkvT, qkvp, QKVW);

    // 2+3) fused RoPE + split-fp16 operand prep
    prep_q<<<(Mrows * 1024 + 255) / 256, 256>>>(qkvp, qhp, qlp);
    prep_k<<<(Mrows * 256 + 255) / 256, 256>>>(qkvp, khp, klp);
    prep_vt<<<dim3(Dh / 32, Sq / 32, Bq * NKVq), dim3(32, 8)>>>(qkvp, vthp, vtlp);

    // 4) attention (split fp16 MMA, double-buffered; epilogue emits frag tiles)
    attn_kernel<<<dim3(Sq / 64, Bq * NHq), 256, ATTN_SMEM>>>(qhp, qlp, khp, klp,
                                                             vthp, vtlp, attp);

    // 5) output GEMM
    mma_gemm<<<dim3(H_DIM / 128, Mrows / 128), 256, GEMM_SMEM>>>(attp, woT, out, H_DIM);
}

// round 14
// speedup vs baseline: 1.0404x; 1.0404x over previous
#include <cuda_runtime.h>
#include <cuda_fp16.h>
#include <math.h>
#include <stdint.h>

#define H_DIM 4096
#define QKVW  6144          // (NH + 2*NKV) * D
#define NHq   32
#define NKVq  8
#define Dh    128
#define Sq    2048
#define Bq    2
#define Mrows 4096          // B * S
#define GK    4096          // K dim of both big GEMMs

// GEMM pipeline: 3 stages x 32KB = 96KB -> 2 CTAs/SM
#define NSTG 3
#define STAGE_BYTES 32768
#define NIT  (GK / 64)

// attention smem layout (bytes) — K double-buffered hi/lo, VT double-buffered hi-only
#define SM_QH 0            // 16KB
#define SM_QL 16384        // 16KB
#define SM_K  32768        // 2 bufs x (KH 16KB + KL 16KB) = 64KB
#define SM_VT 98304        // 2 bufs x (VTH 16KB) = 32KB
#define SM_PH 131072       // 8KB
#define SM_SS 139264       // fp32 scores 64 x 66 = 16896B
#define SM_MS 156160
#define SM_LS 156416
#define SM_CS 156672
#define ATTN_SMEM 156928

// scratch (device globals: allocation-guard compliant)
__device__ float  g_qkv[(size_t)Mrows * QKVW];
__device__ __half g_att[(size_t)Mrows * (NHq * Dh)];
__device__ __half g_hsr[(size_t)Mrows * H_DIM];
__device__ __half g_wqkvT[(size_t)QKVW * H_DIM];
__device__ __half g_woT[(size_t)H_DIM * H_DIM];
// attention operands (q,k hi/lo fp16 split; v fp16 only)
__device__ __half g_qh[(size_t)Mrows * (NHq * Dh)];
__device__ __half g_ql[(size_t)Mrows * (NHq * Dh)];
__device__ __half g_kh[(size_t)Mrows * (NKVq * Dh)];
__device__ __half g_kl[(size_t)Mrows * (NKVq * Dh)];
__device__ __half g_vth[(size_t)Mrows * (NKVq * Dh)];   // [b][kvh][d][s]

// ===========================================================================
// helpers (sm_80-era PTX only)
// ===========================================================================
__device__ __forceinline__ uint32_t smem_u32(const void* p) {
    uint32_t a;
    asm("{ .reg .u64 t; cvta.to.shared.u64 t, %1; cvt.u32.u64 %0, t; }" : "=r"(a) : "l"(p));
    return a;
}
__device__ __forceinline__ uint32_t lds32(uint32_t a) {
    uint32_t v; asm volatile("ld.shared.b32 %0, [%1];" : "=r"(v) : "r"(a)); return v;
}
__device__ __forceinline__ void sts128(uint32_t a, uint4 v) {
    asm volatile("st.shared.v4.b32 [%0], {%1,%2,%3,%4};"
                 :: "r"(a), "r"(v.x), "r"(v.y), "r"(v.z), "r"(v.w) : "memory");
}
#define CP16(smaddr, gptr) \
    asm volatile("cp.async.cg.shared.global [%0], [%1], 16;" :: "r"(smaddr), "l"(gptr) : "memory")
#define CP_COMMIT() asm volatile("cp.async.commit_group;" ::: "memory")
#define CP_WAIT(n)  asm volatile("cp.async.wait_group %0;" :: "n"(n) : "memory")

// fp16 m16n8k16 MMA, fp32 accumulate
__device__ __forceinline__ void mma_f16(float* d, const uint32_t* a, const uint32_t* b) {
    asm volatile("mma.sync.aligned.m16n8k16.row.col.f32.f16.f16.f32 "
                 "{%0,%1,%2,%3}, {%4,%5,%6,%7}, {%8,%9}, {%0,%1,%2,%3};"
                 : "+f"(d[0]), "+f"(d[1]), "+f"(d[2]), "+f"(d[3])
                 : "r"(a[0]), "r"(a[1]), "r"(a[2]), "r"(a[3]), "r"(b[0]), "r"(b[1]));
}

// ===========================================================================
// fp16 mma.sync GEMM (R9/R11-proven: scalar-LDS fragments, 3-stage, 2 CTAs/SM)
// ===========================================================================
__global__ __launch_bounds__(256, 2) void mma_gemm(const __half* __restrict__ A,
                                                   const __half* __restrict__ BT,
                                                   float* __restrict__ C, int Ntot) {
    extern __shared__ char smraw[];
    const uint32_t SB = smem_u32(smraw);

    int tid  = threadIdx.x;
    int lane = tid & 31, wid = tid >> 5;
    int wm = wid & 1, wn = wid >> 1;
    int g  = lane >> 2, q = lane & 3;

    int l = blockIdx.y * gridDim.x + blockIdx.x;
    int per = gridDim.y << 3;
    int gq = l / per, rr = l - gq * per;
    int ntile = (gq << 3) + (rr & 7);
    int mtile = rr >> 3;

    int lrow = tid >> 1;
    int lc0  = (tid & 1) << 2;
    const char* gaRow = (const char*)(A  + (size_t)(mtile * 128 + lrow) * GK);
    const char* gbRow = (const char*)(BT + (size_t)(ntile * 128 + lrow) * GK);
    uint32_t sArow = lrow * 128;
    uint32_t sBrow = 16384 + lrow * 128;
    int rsw = lrow & 7;

    uint32_t rowAoff[4], rowBoff[4];
#pragma unroll
    for (int i = 0; i < 4; i++)
        rowAoff[i] = (uint32_t)((wm * 64 + i * 16 + g) * 128 + q * 4);
#pragma unroll
    for (int j = 0; j < 4; j++)
        rowBoff[j] = (uint32_t)(16384 + (wn * 32 + j * 8 + g) * 128 + q * 4);

    float acc[4][4][4] = {};

#pragma unroll
    for (int p = 0; p < NSTG - 1; p++) {
        uint32_t as = SB + p * STAGE_BYTES;
#pragma unroll
        for (int j = 0; j < 4; j++) {
            int c = lc0 + j;
            uint32_t so = (uint32_t)((c ^ rsw) << 4);
            CP16(as + sArow + so, gaRow + p * 128 + c * 16);
            CP16(as + sBrow + so, gbRow + p * 128 + c * 16);
        }
        CP_COMMIT();
    }

    int scur = 0, spf = NSTG - 1;
    for (int it = 0; it < NIT; it++) {
        CP_WAIT(NSTG - 2);
        __syncthreads();

        int pf = it + NSTG - 1;
        if (pf < NIT) {
            uint32_t as = SB + spf * STAGE_BYTES;
#pragma unroll
            for (int j = 0; j < 4; j++) {
                int c = lc0 + j;
                uint32_t so = (uint32_t)((c ^ rsw) << 4);
                CP16(as + sArow + so, gaRow + pf * 128 + c * 16);
                CP16(as + sBrow + so, gbRow + pf * 128 + c * 16);
            }
        }
        CP_COMMIT();

        uint32_t stage = SB + scur * STAGE_BYTES;
#pragma unroll
        for (int ks = 0; ks < 4; ks++) {
            uint32_t o0 = (uint32_t)(((2 * ks) ^ g) << 4);
            uint32_t o1 = (uint32_t)(((2 * ks + 1) ^ g) << 4);
            uint32_t afr[4][4], bfr[4][2];
#pragma unroll
            for (int i = 0; i < 4; i++) {
                uint32_t ra = stage + rowAoff[i];
                afr[i][0] = lds32(ra + o0);
                afr[i][1] = lds32(ra + 1024 + o0);
                afr[i][2] = lds32(ra + o1);
                afr[i][3] = lds32(ra + 1024 + o1);
            }
#pragma unroll
            for (int j = 0; j < 4; j++) {
                uint32_t rb = stage + rowBoff[j];
                bfr[j][0] = lds32(rb + o0);
                bfr[j][1] = lds32(rb + o1);
            }
#pragma unroll
            for (int i = 0; i < 4; i++)
#pragma unroll
                for (int j = 0; j < 4; j++)
                    mma_f16(acc[i][j], afr[i], bfr[j]);
        }

        if (++scur == NSTG) scur = 0;
        if (++spf == NSTG) spf = 0;
    }

    float* Cp = C + (size_t)(mtile * 128 + wm * 64 + g) * Ntot + ntile * 128 + wn * 32 + q * 2;
#pragma unroll
    for (int i = 0; i < 4; i++)
#pragma unroll
        for (int j = 0; j < 4; j++) {
            *(float2*)(Cp + (size_t)(i * 16) * Ntot + j * 8)     = make_float2(acc[i][j][0], acc[i][j][1]);
            *(float2*)(Cp + (size_t)(i * 16 + 8) * Ntot + j * 8) = make_float2(acc[i][j][2], acc[i][j][3]);
        }
}

// ===========================================================================
// prep kernels (R11-proven)
// ===========================================================================
__global__ void transpose_half(const float* __restrict__ in, __half* __restrict__ out,
                               int R, int C) {
    __shared__ float t[32][33];
    int x = blockIdx.x * 32 + threadIdx.x;
    int y0 = blockIdx.y * 32;
#pragma unroll
    for (int j = threadIdx.y; j < 32; j += 8)
        t[j][threadIdx.x] = in[(size_t)(y0 + j) * C + x];
    __syncthreads();
    int xo = y0 + threadIdx.x;
    int yo0 = blockIdx.x * 32;
#pragma unroll
    for (int j = threadIdx.y; j < 32; j += 8)
        out[(size_t)(yo0 + j) * R + xo] = __float2half_rn(t[threadIdx.x][j]);
}

__global__ void to_half_kernel(const float* __restrict__ in, __half* __restrict__ out, int n4) {
    int i = blockIdx.x * blockDim.x + threadIdx.x;
    if (i >= n4) return;
    float4 v = ((const float4*)in)[i];
    __half2 h0 = __floats2half2_rn(v.x, v.y);
    __half2 h1 = __floats2half2_rn(v.z, v.w);
    ((uint2*)out)[i] = make_uint2(*(uint32_t*)&h0, *(uint32_t*)&h1);
}

__global__ void prep_q(const float* __restrict__ qkv,
                       __half* __restrict__ qh, __half* __restrict__ ql) {
    const float scale = 0.08838834764831845f;
    int t = blockIdx.x * blockDim.x + threadIdx.x;
    if (t >= Mrows * (NHq * Dh / 4)) return;
    int m = t / 1024;
    int cc = (t % 1024) * 4;
    int h = cc >> 7, d = cc & 127;
    int b = m >> 11, s = m & 2047;
    float4 v = *(const float4*)(qkv + (size_t)m * QKVW + cc);
    float f[4];
    {
        int p0 = d >> 1;
        float i0 = exp2f(-(float)p0 * (13.287712379549449f / 64.0f));
        float i1 = exp2f(-(float)(p0 + 1) * (13.287712379549449f / 64.0f));
        float sn0, cs0, sn1, cs1;
        sincosf((float)s * i0, &sn0, &cs0);
        sincosf((float)s * i1, &sn1, &cs1);
        f[0] = (v.x * cs0 - v.y * sn0) * scale;
        f[1] = (v.y * cs0 + v.x * sn0) * scale;
        f[2] = (v.z * cs1 - v.w * sn1) * scale;
        f[3] = (v.w * cs1 + v.z * sn1) * scale;
    }
    size_t o = ((size_t)((b * NHq + h) * Sq + s)) * Dh + d;
    __half hh[4], hl[4];
#pragma unroll
    for (int i = 0; i < 4; i++) {
        hh[i] = __float2half_rn(f[i]);
        hl[i] = __float2half_rn(f[i] - __half2float(hh[i]));
    }
    *(uint2*)(qh + o) = *(uint2*)hh;
    *(uint2*)(ql + o) = *(uint2*)hl;
}

__global__ void prep_k(const float* __restrict__ qkv,
                       __half* __restrict__ kh, __half* __restrict__ kl) {
    int t = blockIdx.x * blockDim.x + threadIdx.x;
    if (t >= Mrows * (NKVq * Dh / 4)) return;
    int m = t / 256;
    int cc = (t % 256) * 4;
    int kvh = cc >> 7, d = cc & 127;
    int b = m >> 11, s = m & 2047;
    float4 v = *(const float4*)(qkv + (size_t)m * QKVW + NHq * Dh + cc);
    float f[4];
    {
        int p0 = d >> 1;
        float i0 = exp2f(-(float)p0 * (13.287712379549449f / 64.0f));
        float i1 = exp2f(-(float)(p0 + 1) * (13.287712379549449f / 64.0f));
        float sn0, cs0, sn1, cs1;
        sincosf((float)s * i0, &sn0, &cs0);
        sincosf((float)s * i1, &sn1, &cs1);
        f[0] = v.x * cs0 - v.y * sn0;
        f[1] = v.y * cs0 + v.x * sn0;
        f[2] = v.z * cs1 - v.w * sn1;
        f[3] = v.w * cs1 + v.z * sn1;
    }
    size_t o = ((size_t)((b * NKVq + kvh) * Sq + s)) * Dh + d;
    __half hh[4], hl[4];
#pragma unroll
    for (int i = 0; i < 4; i++) {
        hh[i] = __float2half_rn(f[i]);
        hl[i] = __float2half_rn(f[i] - __half2float(hh[i]));
    }
    *(uint2*)(kh + o) = *(uint2*)hh;
    *(uint2*)(kl + o) = *(uint2*)hl;
}

// v part -> transposed [b][kvh][d][s] fp16 (single precision)
__global__ void prep_vt(const float* __restrict__ qkv, __half* __restrict__ vth) {
    __shared__ float t[32][33];
    int bk = blockIdx.z;
    int b = bk >> 3, kvh = bk & 7;
    int x = blockIdx.x * 32 + threadIdx.x;   // d
    int y0 = blockIdx.y * 32;                // s
    const float* src = qkv + (size_t)(b * Sq) * QKVW + (NHq + NKVq) * Dh + kvh * Dh;
#pragma unroll
    for (int j = threadIdx.y; j < 32; j += 8)
        t[j][threadIdx.x] = src[(size_t)(y0 + j) * QKVW + x];
    __syncthreads();
    int xo = y0 + threadIdx.x;      // s
    int yo0 = blockIdx.x * 32;      // d
#pragma unroll
    for (int j = threadIdx.y; j < 32; j += 8) {
        float v = t[threadIdx.x][j];
        int d = yo0 + j;
        vth[((size_t)bk * Dh + d) * Sq + xo] = __float2half_rn(v);
    }
}

// ===========================================================================
// Causal GQA flash attention: split-fp16 QK^T, single-fp16 PV,
// K(hi/lo) + V(hi) double-buffered cp.async.
// ===========================================================================
__global__ __launch_bounds__(256) void attn_kernel(const __half* __restrict__ qh,
                                                   const __half* __restrict__ ql,
                                                   const __half* __restrict__ kh,
                                                   const __half* __restrict__ kl,
                                                   const __half* __restrict__ vth,
                                                   __half* __restrict__ att) {
    extern __shared__ char smc[];
    const uint32_t SMB = smem_u32(smc);
    float* Ss  = (float*)(smc + SM_SS);
    float* m_s = (float*)(smc + SM_MS);
    float* l_s = (float*)(smc + SM_LS);
    float* c_s = (float*)(smc + SM_CS);

    int tid  = threadIdx.x;
    int lane = tid & 31, wid = tid >> 5;
    int g = lane >> 2, q = lane & 3;
    int wm = wid & 1, wn = wid >> 1;

    int qtile = blockIdx.x;
    int bh    = blockIdx.y;
    int b     = bh >> 5;
    int h     = bh & 31;
    int kvh   = h >> 2;

    const __half* qhb = qh + ((size_t)((b * NHq + h) * Sq + qtile * 64)) * Dh;
    const __half* qlb = ql + ((size_t)((b * NHq + h) * Sq + qtile * 64)) * Dh;
    const __half* khb = kh + ((size_t)((b * NKVq + kvh) * Sq)) * Dh;
    const __half* klb = kl + ((size_t)((b * NKVq + kvh) * Sq)) * Dh;
    const __half* vthb = vth + ((size_t)(b * NKVq + kvh) * Dh) * Sq;

    int krow = tid >> 2, kc0 = (tid & 3) * 4;
    int vrow = tid >> 1, vc0 = (tid & 1) * 4;

    // --- load Q tiles + KV[0]
    {
#pragma unroll
        for (int cc = 0; cc < 4; cc++) {
            int c = kc0 + cc;
            int kc = c >> 3;
            uint32_t so = (uint32_t)(((c & 7) ^ (krow & 7)) << 4);
            uint32_t dst = SMB + kc * 8192 + krow * 128 + so;
            CP16(dst + SM_QH, (const char*)(qhb + (size_t)krow * Dh + c * 8));
            CP16(dst + SM_QL, (const char*)(qlb + (size_t)krow * Dh + c * 8));
        }
        const __half* kph = khb + (size_t)krow * Dh;
        const __half* kpl = klb + (size_t)krow * Dh;
#pragma unroll
        for (int cc = 0; cc < 4; cc++) {
            int c = kc0 + cc;
            int kc = c >> 3;
            uint32_t so = (uint32_t)(((c & 7) ^ (krow & 7)) << 4);
            uint32_t dst = SMB + SM_K + kc * 8192 + krow * 128 + so;
            CP16(dst, (const char*)(kph + c * 8));
            CP16(dst + 16384, (const char*)(kpl + c * 8));
        }
        const __half* vph = vthb + (size_t)vrow * Sq;
#pragma unroll
        for (int cc = 0; cc < 4; cc++) {
            int c = vc0 + cc;
            uint32_t so = (uint32_t)((c ^ (vrow & 7)) << 4);
            CP16(SMB + SM_VT + vrow * 128 + so, (const char*)(vph + c * 8));
        }
        CP_COMMIT();
    }
    if (tid < 64) { m_s[tid] = -1e30f; l_s[tid] = 0.0f; }

    int srow = tid >> 2, ssub = tid & 3;

    uint32_t qAoff[2], kBoff[2], pAoff[2], vBoff[4];
#pragma unroll
    for (int i = 0; i < 2; i++) {
        qAoff[i] = (uint32_t)((wm * 32 + i * 16 + g) * 128 + q * 4);
        pAoff[i] = qAoff[i];
    }
#pragma unroll
    for (int j = 0; j < 2; j++)
        kBoff[j] = (uint32_t)((wn * 16 + j * 8 + g) * 128 + q * 4);
#pragma unroll
    for (int j = 0; j < 4; j++)
        vBoff[j] = (uint32_t)((wn * 32 + j * 8 + g) * 128 + q * 4);

    float oacc[2][4][4] = {};

    for (int kt = 0; kt <= qtile; kt++) {
        __syncthreads();

        if (kt < qtile) {
            uint32_t kb = SMB + SM_K + ((kt + 1) & 1) * 32768;
            uint32_t vb = SMB + SM_VT + ((kt + 1) & 1) * 16384;
            const __half* kph = khb + (size_t)((kt + 1) * 64 + krow) * Dh;
            const __half* kpl = klb + (size_t)((kt + 1) * 64 + krow) * Dh;
#pragma unroll
            for (int cc = 0; cc < 4; cc++) {
                int c = kc0 + cc;
                int kc = c >> 3;
                uint32_t so = (uint32_t)(((c & 7) ^ (krow & 7)) << 4);
                uint32_t dst = kb + kc * 8192 + krow * 128 + so;
                CP16(dst, (const char*)(kph + c * 8));
                CP16(dst + 16384, (const char*)(kpl + c * 8));
            }
            const __half* vph = vthb + (size_t)vrow * Sq + (kt + 1) * 64;
#pragma unroll
            for (int cc = 0; cc < 4; cc++) {
                int c = vc0 + cc;
                uint32_t so = (uint32_t)((c ^ (vrow & 7)) << 4);
                CP16(vb + vrow * 128 + so, (const char*)(vph + c * 8));
            }
            CP_COMMIT();
            CP_WAIT(1);
        } else {
            CP_WAIT(0);
        }
        __syncthreads();

        uint32_t KB = SMB + SM_K + (kt & 1) * 32768;
        uint32_t VB = SMB + SM_VT + (kt & 1) * 16384;

        // --- QK^T: split fp16 MMA (Qh*Kh + Qh*Kl + Ql*Kh)
        float sacc[2][2][4] = {};
#pragma unroll
        for (int kc = 0; kc < 2; kc++) {
            uint32_t qbh = SMB + SM_QH + kc * 8192, qbl = SMB + SM_QL + kc * 8192;
            uint32_t kbh = KB + kc * 8192, kbl = KB + 16384 + kc * 8192;
#pragma unroll
            for (int ks = 0; ks < 4; ks++) {
                uint32_t o0 = (uint32_t)(((2 * ks) ^ g) << 4);
                uint32_t o1 = (uint32_t)(((2 * ks + 1) ^ g) << 4);
                uint32_t aH[2][4], aL[2][4], bH[2][2], bL[2][2];
#pragma unroll
                for (int i = 0; i < 2; i++) {
                    uint32_t rh = qbh + qAoff[i], rl2 = qbl + qAoff[i];
                    aH[i][0] = lds32(rh + o0); aH[i][1] = lds32(rh + 1024 + o0);
                    aH[i][2] = lds32(rh + o1); aH[i][3] = lds32(rh + 1024 + o1);
                    aL[i][0] = lds32(rl2 + o0); aL[i][1] = lds32(rl2 + 1024 + o0);
                    aL[i][2] = lds32(rl2 + o1); aL[i][3] = lds32(rl2 + 1024 + o1);
                }
#pragma unroll
                for (int j = 0; j < 2; j++) {
                    uint32_t rh = kbh + kBoff[j], rl2 = kbl + kBoff[j];
                    bH[j][0] = lds32(rh + o0); bH[j][1] = lds32(rh + o1);
                    bL[j][0] = lds32(rl2 + o0); bL[j][1] = lds32(rl2 + o1);
                }
#pragma unroll
                for (int i = 0; i < 2; i++)
#pragma unroll
                    for (int j = 0; j < 2; j++) {
                        mma_f16(sacc[i][j], aH[i], bH[j]);
                        mma_f16(sacc[i][j], aH[i], bL[j]);
                        mma_f16(sacc[i][j], aL[i], bH[j]);
                    }
            }
        }
#pragma unroll
        for (int i = 0; i < 2; i++)
#pragma unroll
            for (int j = 0; j < 2; j++) {
                int r0 = wm * 32 + i * 16 + g;
                int cc = wn * 16 + j * 8 + 2 * q;
                *(float2*)&Ss[r0 * 66 + cc]       = make_float2(sacc[i][j][0], sacc[i][j][1]);
                *(float2*)&Ss[(r0 + 8) * 66 + cc] = make_float2(sacc[i][j][2], sacc[i][j][3]);
            }
        __syncthreads();

        // --- online softmax (4 threads/row), write P fp16
        {
            int limit = (kt == qtile) ? srow : 63;
            float tm = -1e30f;
            float pv_[16];
#pragma unroll
            for (int j = 0; j < 16; j++) {
                int c = ssub * 16 + j;
                float v = Ss[srow * 66 + c];
                if (c <= limit) tm = fmaxf(tm, v);
            }
            tm = fmaxf(tm, __shfl_xor_sync(0xFFFFFFFFu, tm, 1));
            tm = fmaxf(tm, __shfl_xor_sync(0xFFFFFFFFu, tm, 2));
            float mold = m_s[srow];
            float mnew = fmaxf(mold, tm);
            float sum = 0.0f;
#pragma unroll
            for (int j = 0; j < 16; j++) {
                int c = ssub * 16 + j;
                float p = (c <= limit) ? __expf(Ss[srow * 66 + c] - mnew) : 0.0f;
                pv_[j] = p;
                sum += p;
            }
#pragma unroll
            for (int c2 = 0; c2 < 2; c2++) {
                int c = ssub * 2 + c2;
                uint32_t hw[4];
#pragma unroll
                for (int t2 = 0; t2 < 4; t2++) {
                    __half2 hh = __floats2half2_rn(pv_[c2 * 8 + 2 * t2], pv_[c2 * 8 + 2 * t2 + 1]);
                    hw[t2] = *(uint32_t*)&hh;
                }
                uint32_t so = (uint32_t)((c ^ (srow & 7)) << 4);
                sts128(SMB + SM_PH + srow * 128 + so, make_uint4(hw[0], hw[1], hw[2], hw[3]));
            }
            sum += __shfl_xor_sync(0xFFFFFFFFu, sum, 1);
            sum += __shfl_xor_sync(0xFFFFFFFFu, sum, 2);
            if (ssub == 0) {
                float corr = __expf(mold - mnew);
                l_s[srow] = l_s[srow] * corr + sum;
                m_s[srow] = mnew;
                c_s[srow] = corr;
            }
        }
        __syncthreads();

        // --- O rescale, then O += P @ VT (single fp16 MMA)
        float cr0[2], cr1[2];
#pragma unroll
        for (int i = 0; i < 2; i++) {
            cr0[i] = c_s[wm * 32 + i * 16 + g];
            cr1[i] = c_s[wm * 32 + i * 16 + 8 + g];
        }
#pragma unroll
        for (int i = 0; i < 2; i++)
#pragma unroll
            for (int j = 0; j < 4; j++) {
                oacc[i][j][0] *= cr0[i]; oacc[i][j][1] *= cr0[i];
                oacc[i][j][2] *= cr1[i]; oacc[i][j][3] *= cr1[i];
            }

#pragma unroll
        for (int ks = 0; ks < 4; ks++) {
            uint32_t o0 = (uint32_t)(((2 * ks) ^ g) << 4);
            uint32_t o1 = (uint32_t)(((2 * ks + 1) ^ g) << 4);
            uint32_t aH[2][4], bH[4][2];
#pragma unroll
            for (int i = 0; i < 2; i++) {
                uint32_t rh = SMB + SM_PH + pAoff[i];
                aH[i][0] = lds32(rh + o0); aH[i][1] = lds32(rh + 1024 + o0);
                aH[i][2] = lds32(rh + o1); aH[i][3] = lds32(rh + 1024 + o1);
            }
#pragma unroll
            for (int j = 0; j < 4; j++) {
                uint32_t rh = VB + vBoff[j];
                bH[j][0] = lds32(rh + o0); bH[j][1] = lds32(rh + o1);
            }
#pragma unroll
            for (int i = 0; i < 2; i++)
#pragma unroll
                for (int j = 0; j < 4; j++)
                    mma_f16(oacc[i][j], aH[i], bH[j]);
        }
    }

    // --- epilogue: O / l -> fp16 att
#pragma unroll
    for (int i = 0; i < 2; i++) {
        int ra = wm * 32 + i * 16 + g;
        float la = 1.0f / l_s[ra];
        float lb = 1.0f / l_s[ra + 8];
        __half* oa = att + (size_t)(b * Sq + qtile * 64 + ra) * (NHq * Dh) + h * Dh;
        __half* ob = att + (size_t)(b * Sq + qtile * 64 + ra + 8) * (NHq * Dh) + h * Dh;
#pragma unroll
        for (int j = 0; j < 4; j++) {
            int cc = wn * 32 + j * 8 + 2 * q;
            __half2 va = __floats2half2_rn(oacc[i][j][0] * la, oacc[i][j][1] * la);
            __half2 vb = __floats2half2_rn(oacc[i][j][2] * lb, oacc[i][j][3] * lb);
            *(__half2*)(oa + cc) = va;
            *(__half2*)(ob + cc) = vb;
        }
    }
}

// ===========================================================================
extern "C" void kernel_launch(void* const* d_in, const int* in_sizes, int n_in,
                              void* d_out, int out_size) {
    const float* hs   = (const float*)d_in[0];
    const float* wqkv = (const float*)d_in[2];
    const float* wo   = (const float*)d_in[3];
    float* out = (float*)d_out;

    float* qkvp;
    __half *attp, *hsr, *wqkvT, *woT, *qhp, *qlp, *khp, *klp, *vthp;
    cudaGetSymbolAddress((void**)&qkvp, g_qkv);
    cudaGetSymbolAddress((void**)&attp, g_att);
    cudaGetSymbolAddress((void**)&hsr, g_hsr);
    cudaGetSymbolAddress((void**)&wqkvT, g_wqkvT);
    cudaGetSymbolAddress((void**)&woT, g_woT);
    cudaGetSymbolAddress((void**)&qhp, g_qh);
    cudaGetSymbolAddress((void**)&qlp, g_ql);
    cudaGetSymbolAddress((void**)&khp, g_kh);
    cudaGetSymbolAddress((void**)&klp, g_kl);
    cudaGetSymbolAddress((void**)&vthp, g_vth);

    const int GEMM_SMEM = NSTG * STAGE_BYTES;   // 96 KB
    cudaFuncSetAttribute((const void*)mma_gemm,
                         cudaFuncAttributeMaxDynamicSharedMemorySize, GEMM_SMEM);
    cudaFuncSetAttribute((const void*)attn_kernel,
                         cudaFuncAttributeMaxDynamicSharedMemorySize, ATTN_SMEM);

    // 0) operand prep for GEMM1
    transpose_half<<<dim3(QKVW / 32, H_DIM / 32), dim3(32, 8)>>>(wqkv, wqkvT, H_DIM, QKVW);
    transpose_half<<<dim3(H_DIM / 32, H_DIM / 32), dim3(32, 8)>>>(wo, woT, H_DIM, H_DIM);
    to_half_kernel<<<(Mrows * H_DIM / 4 + 255) / 256, 256>>>(hs, hsr, Mrows * H_DIM / 4);

    // 1) QKV GEMM
    mma_gemm<<<dim3(QKVW / 128, Mrows / 128), 256, GEMM_SMEM>>>(hsr, wqkvT, qkvp, QKVW);

    // 2+3) fused RoPE + split-fp16 operand prep
    prep_q<<<(Mrows * 1024 + 255) / 256, 256>>>(qkvp, qhp, qlp);
    prep_k<<<(Mrows * 256 + 255) / 256, 256>>>(qkvp, khp, klp);
    prep_vt<<<dim3(Dh / 32, Sq / 32, Bq * NKVq), dim3(32, 8)>>>(qkvp, vthp);

    // 4) attention (split-fp16 QK^T, single-fp16 PV, double-buffered)
    attn_kernel<<<dim3(Sq / 64, Bq * NHq), 256, ATTN_SMEM>>>(qhp, qlp, khp, klp,
                                                             vthp, attp);

    // 5) output GEMM
    mma_gemm<<<dim3(H_DIM / 128, Mrows / 128), 256, GEMM_SMEM>>>(attp, woT, out, H_DIM);
}

// round 15
// speedup vs baseline: 1.6533x; 1.5891x over previous
#include <cuda_runtime.h>
#include <cuda_fp16.h>
#include <math.h>
#include <stdint.h>

#define H_DIM 4096
#define QKVW  6144          // (NH + 2*NKV) * D
#define NHq   32
#define NKVq  8
#define Dh    128
#define Sq    2048
#define Bq    2
#define Mrows 4096          // B * S
#define GK    4096          // K dim of both big GEMMs

// GEMM pipeline: 3 stages x 32KB = 96KB -> 2 CTAs/SM
#define NSTG 3
#define STAGE_BYTES 32768
#define NIT  (GK / 64)

// attention smem layout (bytes) — single-buffered, 2 CTAs/SM
#define SM_QH 0            // 16KB
#define SM_QL 16384        // 16KB
#define SM_KH 32768        // 16KB
#define SM_KL 49152        // 16KB
#define SM_VT 65536        // 16KB
#define SM_PH 81920        // 8KB
#define SM_SS 90112        // fp32 scores 64 x 66 = 16896B
#define SM_MS 107008
#define SM_LS 107264
#define SM_CS 107520
#define ATTN_SMEM 107776

// scratch (device globals: allocation-guard compliant)
__device__ float  g_qkv[(size_t)Mrows * QKVW];
__device__ __half g_att[(size_t)Mrows * (NHq * Dh)];
__device__ __half g_hsr[(size_t)Mrows * H_DIM];
__device__ __half g_wqkvT[(size_t)QKVW * H_DIM];
__device__ __half g_woT[(size_t)H_DIM * H_DIM];
// attention operands (q,k hi/lo fp16 split; v fp16 only)
__device__ __half g_qh[(size_t)Mrows * (NHq * Dh)];
__device__ __half g_ql[(size_t)Mrows * (NHq * Dh)];
__device__ __half g_kh[(size_t)Mrows * (NKVq * Dh)];
__device__ __half g_kl[(size_t)Mrows * (NKVq * Dh)];
__device__ __half g_vth[(size_t)Mrows * (NKVq * Dh)];   // [b][kvh][d][s]

// ===========================================================================
// helpers (sm_80-era PTX only)
// ===========================================================================
__device__ __forceinline__ uint32_t smem_u32(const void* p) {
    uint32_t a;
    asm("{ .reg .u64 t; cvta.to.shared.u64 t, %1; cvt.u32.u64 %0, t; }" : "=r"(a) : "l"(p));
    return a;
}
__device__ __forceinline__ uint32_t lds32(uint32_t a) {
    uint32_t v; asm volatile("ld.shared.b32 %0, [%1];" : "=r"(v) : "r"(a)); return v;
}
__device__ __forceinline__ void sts128(uint32_t a, uint4 v) {
    asm volatile("st.shared.v4.b32 [%0], {%1,%2,%3,%4};"
                 :: "r"(a), "r"(v.x), "r"(v.y), "r"(v.z), "r"(v.w) : "memory");
}
#define CP16(smaddr, gptr) \
    asm volatile("cp.async.cg.shared.global [%0], [%1], 16;" :: "r"(smaddr), "l"(gptr) : "memory")
#define CP_COMMIT() asm volatile("cp.async.commit_group;" ::: "memory")
#define CP_WAIT(n)  asm volatile("cp.async.wait_group %0;" :: "n"(n) : "memory")

// fp16 m16n8k16 MMA, fp32 accumulate
__device__ __forceinline__ void mma_f16(float* d, const uint32_t* a, const uint32_t* b) {
    asm volatile("mma.sync.aligned.m16n8k16.row.col.f32.f16.f16.f32 "
                 "{%0,%1,%2,%3}, {%4,%5,%6,%7}, {%8,%9}, {%0,%1,%2,%3};"
                 : "+f"(d[0]), "+f"(d[1]), "+f"(d[2]), "+f"(d[3])
                 : "r"(a[0]), "r"(a[1]), "r"(a[2]), "r"(a[3]), "r"(b[0]), "r"(b[1]));
}

// ===========================================================================
// fp16 mma.sync GEMM (R9/R11-proven: scalar-LDS fragments, 3-stage, 2 CTAs/SM)
// ===========================================================================
__global__ __launch_bounds__(256, 2) void mma_gemm(const __half* __restrict__ A,
                                                   const __half* __restrict__ BT,
                                                   float* __restrict__ C, int Ntot) {
    extern __shared__ char smraw[];
    const uint32_t SB = smem_u32(smraw);

    int tid  = threadIdx.x;
    int lane = tid & 31, wid = tid >> 5;
    int wm = wid & 1, wn = wid >> 1;
    int g  = lane >> 2, q = lane & 3;

    int l = blockIdx.y * gridDim.x + blockIdx.x;
    int per = gridDim.y << 3;
    int gq = l / per, rr = l - gq * per;
    int ntile = (gq << 3) + (rr & 7);
    int mtile = rr >> 3;

    int lrow = tid >> 1;
    int lc0  = (tid & 1) << 2;
    const char* gaRow = (const char*)(A  + (size_t)(mtile * 128 + lrow) * GK);
    const char* gbRow = (const char*)(BT + (size_t)(ntile * 128 + lrow) * GK);
    uint32_t sArow = lrow * 128;
    uint32_t sBrow = 16384 + lrow * 128;
    int rsw = lrow & 7;

    uint32_t rowAoff[4], rowBoff[4];
#pragma unroll
    for (int i = 0; i < 4; i++)
        rowAoff[i] = (uint32_t)((wm * 64 + i * 16 + g) * 128 + q * 4);
#pragma unroll
    for (int j = 0; j < 4; j++)
        rowBoff[j] = (uint32_t)(16384 + (wn * 32 + j * 8 + g) * 128 + q * 4);

    float acc[4][4][4] = {};

#pragma unroll
    for (int p = 0; p < NSTG - 1; p++) {
        uint32_t as = SB + p * STAGE_BYTES;
#pragma unroll
        for (int j = 0; j < 4; j++) {
            int c = lc0 + j;
            uint32_t so = (uint32_t)((c ^ rsw) << 4);
            CP16(as + sArow + so, gaRow + p * 128 + c * 16);
            CP16(as + sBrow + so, gbRow + p * 128 + c * 16);
        }
        CP_COMMIT();
    }

    int scur = 0, spf = NSTG - 1;
    for (int it = 0; it < NIT; it++) {
        CP_WAIT(NSTG - 2);
        __syncthreads();

        int pf = it + NSTG - 1;
        if (pf < NIT) {
            uint32_t as = SB + spf * STAGE_BYTES;
#pragma unroll
            for (int j = 0; j < 4; j++) {
                int c = lc0 + j;
                uint32_t so = (uint32_t)((c ^ rsw) << 4);
                CP16(as + sArow + so, gaRow + pf * 128 + c * 16);
                CP16(as + sBrow + so, gbRow + pf * 128 + c * 16);
            }
        }
        CP_COMMIT();

        uint32_t stage = SB + scur * STAGE_BYTES;
#pragma unroll
        for (int ks = 0; ks < 4; ks++) {
            uint32_t o0 = (uint32_t)(((2 * ks) ^ g) << 4);
            uint32_t o1 = (uint32_t)(((2 * ks + 1) ^ g) << 4);
            uint32_t afr[4][4], bfr[4][2];
#pragma unroll
            for (int i = 0; i < 4; i++) {
                uint32_t ra = stage + rowAoff[i];
                afr[i][0] = lds32(ra + o0);
                afr[i][1] = lds32(ra + 1024 + o0);
                afr[i][2] = lds32(ra + o1);
                afr[i][3] = lds32(ra + 1024 + o1);
            }
#pragma unroll
            for (int j = 0; j < 4; j++) {
                uint32_t rb = stage + rowBoff[j];
                bfr[j][0] = lds32(rb + o0);
                bfr[j][1] = lds32(rb + o1);
            }
#pragma unroll
            for (int i = 0; i < 4; i++)
#pragma unroll
                for (int j = 0; j < 4; j++)
                    mma_f16(acc[i][j], afr[i], bfr[j]);
        }

        if (++scur == NSTG) scur = 0;
        if (++spf == NSTG) spf = 0;
    }

    float* Cp = C + (size_t)(mtile * 128 + wm * 64 + g) * Ntot + ntile * 128 + wn * 32 + q * 2;
#pragma unroll
    for (int i = 0; i < 4; i++)
#pragma unroll
        for (int j = 0; j < 4; j++) {
            *(float2*)(Cp + (size_t)(i * 16) * Ntot + j * 8)     = make_float2(acc[i][j][0], acc[i][j][1]);
            *(float2*)(Cp + (size_t)(i * 16 + 8) * Ntot + j * 8) = make_float2(acc[i][j][2], acc[i][j][3]);
        }
}

// ===========================================================================
// prep kernels (R11-proven)
// ===========================================================================
__global__ void transpose_half(const float* __restrict__ in, __half* __restrict__ out,
                               int R, int C) {
    __shared__ float t[32][33];
    int x = blockIdx.x * 32 + threadIdx.x;
    int y0 = blockIdx.y * 32;
#pragma unroll
    for (int j = threadIdx.y; j < 32; j += 8)
        t[j][threadIdx.x] = in[(size_t)(y0 + j) * C + x];
    __syncthreads();
    int xo = y0 + threadIdx.x;
    int yo0 = blockIdx.x * 32;
#pragma unroll
    for (int j = threadIdx.y; j < 32; j += 8)
        out[(size_t)(yo0 + j) * R + xo] = __float2half_rn(t[threadIdx.x][j]);
}

__global__ void to_half_kernel(const float* __restrict__ in, __half* __restrict__ out, int n4) {
    int i = blockIdx.x * blockDim.x + threadIdx.x;
    if (i >= n4) return;
    float4 v = ((const float4*)in)[i];
    __half2 h0 = __floats2half2_rn(v.x, v.y);
    __half2 h1 = __floats2half2_rn(v.z, v.w);
    ((uint2*)out)[i] = make_uint2(*(uint32_t*)&h0, *(uint32_t*)&h1);
}

__global__ void prep_q(const float* __restrict__ qkv,
                       __half* __restrict__ qh, __half* __restrict__ ql) {
    const float scale = 0.08838834764831845f;
    int t = blockIdx.x * blockDim.x + threadIdx.x;
    if (t >= Mrows * (NHq * Dh / 4)) return;
    int m = t / 1024;
    int cc = (t % 1024) * 4;
    int h = cc >> 7, d = cc & 127;
    int b = m >> 11, s = m & 2047;
    float4 v = *(const float4*)(qkv + (size_t)m * QKVW + cc);
    float f[4];
    {
        int p0 = d >> 1;
        float i0 = exp2f(-(float)p0 * (13.287712379549449f / 64.0f));
        float i1 = exp2f(-(float)(p0 + 1) * (13.287712379549449f / 64.0f));
        float sn0, cs0, sn1, cs1;
        sincosf((float)s * i0, &sn0, &cs0);
        sincosf((float)s * i1, &sn1, &cs1);
        f[0] = (v.x * cs0 - v.y * sn0) * scale;
        f[1] = (v.y * cs0 + v.x * sn0) * scale;
        f[2] = (v.z * cs1 - v.w * sn1) * scale;
        f[3] = (v.w * cs1 + v.z * sn1) * scale;
    }
    size_t o = ((size_t)((b * NHq + h) * Sq + s)) * Dh + d;
    __half hh[4], hl[4];
#pragma unroll
    for (int i = 0; i < 4; i++) {
        hh[i] = __float2half_rn(f[i]);
        hl[i] = __float2half_rn(f[i] - __half2float(hh[i]));
    }
    *(uint2*)(qh + o) = *(uint2*)hh;
    *(uint2*)(ql + o) = *(uint2*)hl;
}

__global__ void prep_k(const float* __restrict__ qkv,
                       __half* __restrict__ kh, __half* __restrict__ kl) {
    int t = blockIdx.x * blockDim.x + threadIdx.x;
    if (t >= Mrows * (NKVq * Dh / 4)) return;
    int m = t / 256;
    int cc = (t % 256) * 4;
    int kvh = cc >> 7, d = cc & 127;
    int b = m >> 11, s = m & 2047;
    float4 v = *(const float4*)(qkv + (size_t)m * QKVW + NHq * Dh + cc);
    float f[4];
    {
        int p0 = d >> 1;
        float i0 = exp2f(-(float)p0 * (13.287712379549449f / 64.0f));
        float i1 = exp2f(-(float)(p0 + 1) * (13.287712379549449f / 64.0f));
        float sn0, cs0, sn1, cs1;
        sincosf((float)s * i0, &sn0, &cs0);
        sincosf((float)s * i1, &sn1, &cs1);
        f[0] = v.x * cs0 - v.y * sn0;
        f[1] = v.y * cs0 + v.x * sn0;
        f[2] = v.z * cs1 - v.w * sn1;
        f[3] = v.w * cs1 + v.z * sn1;
    }
    size_t o = ((size_t)((b * NKVq + kvh) * Sq + s)) * Dh + d;
    __half hh[4], hl[4];
#pragma unroll
    for (int i = 0; i < 4; i++) {
        hh[i] = __float2half_rn(f[i]);
        hl[i] = __float2half_rn(f[i] - __half2float(hh[i]));
    }
    *(uint2*)(kh + o) = *(uint2*)hh;
    *(uint2*)(kl + o) = *(uint2*)hl;
}

// v part -> transposed [b][kvh][d][s] fp16 (single precision)
__global__ void prep_vt(const float* __restrict__ qkv, __half* __restrict__ vth) {
    __shared__ float t[32][33];
    int bk = blockIdx.z;
    int b = bk >> 3, kvh = bk & 7;
    int x = blockIdx.x * 32 + threadIdx.x;   // d
    int y0 = blockIdx.y * 32;                // s
    const float* src = qkv + (size_t)(b * Sq) * QKVW + (NHq + NKVq) * Dh + kvh * Dh;
#pragma unroll
    for (int j = threadIdx.y; j < 32; j += 8)
        t[j][threadIdx.x] = src[(size_t)(y0 + j) * QKVW + x];
    __syncthreads();
    int xo = y0 + threadIdx.x;      // s
    int yo0 = blockIdx.x * 32;      // d
#pragma unroll
    for (int j = threadIdx.y; j < 32; j += 8) {
        float v = t[threadIdx.x][j];
        int d = yo0 + j;
        vth[((size_t)bk * Dh + d) * Sq + xo] = __float2half_rn(v);
    }
}

// ===========================================================================
// Causal GQA flash attention: split-fp16 QK^T, single-fp16 PV,
// single-buffered K/V, 2 CTAs/SM (occupancy hides load latency).
// ===========================================================================
__global__ __launch_bounds__(256, 2) void attn_kernel(const __half* __restrict__ qh,
                                                      const __half* __restrict__ ql,
                                                      const __half* __restrict__ kh,
                                                      const __half* __restrict__ kl,
                                                      const __half* __restrict__ vth,
                                                      __half* __restrict__ att) {
    extern __shared__ char smc[];
    const uint32_t SMB = smem_u32(smc);
    float* Ss  = (float*)(smc + SM_SS);
    float* m_s = (float*)(smc + SM_MS);
    float* l_s = (float*)(smc + SM_LS);
    float* c_s = (float*)(smc + SM_CS);

    int tid  = threadIdx.x;
    int lane = tid & 31, wid = tid >> 5;
    int g = lane >> 2, q = lane & 3;
    int wm = wid & 1, wn = wid >> 1;

    int qtile = blockIdx.x;
    int bh    = blockIdx.y;
    int b     = bh >> 5;
    int h     = bh & 31;
    int kvh   = h >> 2;

    const __half* qhb = qh + ((size_t)((b * NHq + h) * Sq + qtile * 64)) * Dh;
    const __half* qlb = ql + ((size_t)((b * NHq + h) * Sq + qtile * 64)) * Dh;
    const __half* khb = kh + ((size_t)((b * NKVq + kvh) * Sq)) * Dh;
    const __half* klb = kl + ((size_t)((b * NKVq + kvh) * Sq)) * Dh;
    const __half* vthb = vth + ((size_t)(b * NKVq + kvh) * Dh) * Sq;

    int krow = tid >> 2, kc0 = (tid & 3) * 4;
    int vrow = tid >> 1, vc0 = (tid & 1) * 4;

    // --- load Q tiles (once)
    {
#pragma unroll
        for (int cc = 0; cc < 4; cc++) {
            int c = kc0 + cc;
            int kc = c >> 3;
            uint32_t so = (uint32_t)(((c & 7) ^ (krow & 7)) << 4);
            uint32_t dst = SMB + kc * 8192 + krow * 128 + so;
            CP16(dst + SM_QH, (const char*)(qhb + (size_t)krow * Dh + c * 8));
            CP16(dst + SM_QL, (const char*)(qlb + (size_t)krow * Dh + c * 8));
        }
        CP_COMMIT();
    }
    if (tid < 64) { m_s[tid] = -1e30f; l_s[tid] = 0.0f; }

    int srow = tid >> 2, ssub = tid & 3;

    uint32_t qAoff[2], kBoff[2], pAoff[2], vBoff[4];
#pragma unroll
    for (int i = 0; i < 2; i++) {
        qAoff[i] = (uint32_t)((wm * 32 + i * 16 + g) * 128 + q * 4);
        pAoff[i] = qAoff[i];
    }
#pragma unroll
    for (int j = 0; j < 2; j++)
        kBoff[j] = (uint32_t)((wn * 16 + j * 8 + g) * 128 + q * 4);
#pragma unroll
    for (int j = 0; j < 4; j++)
        vBoff[j] = (uint32_t)((wn * 32 + j * 8 + g) * 128 + q * 4);

    float oacc[2][4][4] = {};

    for (int kt = 0; kt <= qtile; kt++) {
        __syncthreads();   // prev iter's K/V reads done: safe to overwrite

        // load K[kt] (hi/lo) + V[kt]
        {
            const __half* kph = khb + (size_t)(kt * 64 + krow) * Dh;
            const __half* kpl = klb + (size_t)(kt * 64 + krow) * Dh;
#pragma unroll
            for (int cc = 0; cc < 4; cc++) {
                int c = kc0 + cc;
                int kc = c >> 3;
                uint32_t so = (uint32_t)(((c & 7) ^ (krow & 7)) << 4);
                uint32_t dst = SMB + SM_KH + kc * 8192 + krow * 128 + so;
                CP16(dst, (const char*)(kph + c * 8));
                CP16(dst + 16384, (const char*)(kpl + c * 8));   // SM_KL
            }
            const __half* vph = vthb + (size_t)vrow * Sq + kt * 64;
#pragma unroll
            for (int cc = 0; cc < 4; cc++) {
                int c = vc0 + cc;
                uint32_t so = (uint32_t)((c ^ (vrow & 7)) << 4);
                CP16(SMB + SM_VT + vrow * 128 + so, (const char*)(vph + c * 8));
            }
            CP_COMMIT();
            CP_WAIT(0);
        }
        __syncthreads();

        // --- QK^T: split fp16 MMA (Qh*Kh + Qh*Kl + Ql*Kh)
        float sacc[2][2][4] = {};
#pragma unroll
        for (int kc = 0; kc < 2; kc++) {
            uint32_t qbh = SMB + SM_QH + kc * 8192, qbl = SMB + SM_QL + kc * 8192;
            uint32_t kbh = SMB + SM_KH + kc * 8192, kbl = SMB + SM_KL + kc * 8192;
#pragma unroll
            for (int ks = 0; ks < 4; ks++) {
                uint32_t o0 = (uint32_t)(((2 * ks) ^ g) << 4);
                uint32_t o1 = (uint32_t)(((2 * ks + 1) ^ g) << 4);
                uint32_t aH[2][4], aL[2][4], bH[2][2], bL[2][2];
#pragma unroll
                for (int i = 0; i < 2; i++) {
                    uint32_t rh = qbh + qAoff[i], rl2 = qbl + qAoff[i];
                    aH[i][0] = lds32(rh + o0); aH[i][1] = lds32(rh + 1024 + o0);
                    aH[i][2] = lds32(rh + o1); aH[i][3] = lds32(rh + 1024 + o1);
                    aL[i][0] = lds32(rl2 + o0); aL[i][1] = lds32(rl2 + 1024 + o0);
                    aL[i][2] = lds32(rl2 + o1); aL[i][3] = lds32(rl2 + 1024 + o1);
                }
#pragma unroll
                for (int j = 0; j < 2; j++) {
                    uint32_t rh = kbh + kBoff[j], rl2 = kbl + kBoff[j];
                    bH[j][0] = lds32(rh + o0); bH[j][1] = lds32(rh + o1);
                    bL[j][0] = lds32(rl2 + o0); bL[j][1] = lds32(rl2 + o1);
                }
#pragma unroll
                for (int i = 0; i < 2; i++)
#pragma unroll
                    for (int j = 0; j < 2; j++) {
                        mma_f16(sacc[i][j], aH[i], bH[j]);
                        mma_f16(sacc[i][j], aH[i], bL[j]);
                        mma_f16(sacc[i][j], aL[i], bH[j]);
                    }
            }
        }
#pragma unroll
        for (int i = 0; i < 2; i++)
#pragma unroll
            for (int j = 0; j < 2; j++) {
                int r0 = wm * 32 + i * 16 + g;
                int cc = wn * 16 + j * 8 + 2 * q;
                *(float2*)&Ss[r0 * 66 + cc]       = make_float2(sacc[i][j][0], sacc[i][j][1]);
                *(float2*)&Ss[(r0 + 8) * 66 + cc] = make_float2(sacc[i][j][2], sacc[i][j][3]);
            }
        __syncthreads();

        // --- online softmax (4 threads/row), write P fp16
        {
            int limit = (kt == qtile) ? srow : 63;
            float tm = -1e30f;
            float pv_[16];
#pragma unroll
            for (int j = 0; j < 16; j++) {
                int c = ssub * 16 + j;
                float v = Ss[srow * 66 + c];
                if (c <= limit) tm = fmaxf(tm, v);
            }
            tm = fmaxf(tm, __shfl_xor_sync(0xFFFFFFFFu, tm, 1));
            tm = fmaxf(tm, __shfl_xor_sync(0xFFFFFFFFu, tm, 2));
            float mold = m_s[srow];
            float mnew = fmaxf(mold, tm);
            float sum = 0.0f;
#pragma unroll
            for (int j = 0; j < 16; j++) {
                int c = ssub * 16 + j;
                float p = (c <= limit) ? __expf(Ss[srow * 66 + c] - mnew) : 0.0f;
                pv_[j] = p;
                sum += p;
            }
#pragma unroll
            for (int c2 = 0; c2 < 2; c2++) {
                int c = ssub * 2 + c2;
                uint32_t hw[4];
#pragma unroll
                for (int t2 = 0; t2 < 4; t2++) {
                    __half2 hh = __floats2half2_rn(pv_[c2 * 8 + 2 * t2], pv_[c2 * 8 + 2 * t2 + 1]);
                    hw[t2] = *(uint32_t*)&hh;
                }
                uint32_t so = (uint32_t)((c ^ (srow & 7)) << 4);
                sts128(SMB + SM_PH + srow * 128 + so, make_uint4(hw[0], hw[1], hw[2], hw[3]));
            }
            sum += __shfl_xor_sync(0xFFFFFFFFu, sum, 1);
            sum += __shfl_xor_sync(0xFFFFFFFFu, sum, 2);
            if (ssub == 0) {
                float corr = __expf(mold - mnew);
                l_s[srow] = l_s[srow] * corr + sum;
                m_s[srow] = mnew;
                c_s[srow] = corr;
            }
        }
        __syncthreads();

        // --- O rescale, then O += P @ VT (single fp16 MMA)
        float cr0[2], cr1[2];
#pragma unroll
        for (int i = 0; i < 2; i++) {
            cr0[i] = c_s[wm * 32 + i * 16 + g];
            cr1[i] = c_s[wm * 32 + i * 16 + 8 + g];
        }
#pragma unroll
        for (int i = 0; i < 2; i++)
#pragma unroll
            for (int j = 0; j < 4; j++) {
                oacc[i][j][0] *= cr0[i]; oacc[i][j][1] *= cr0[i];
                oacc[i][j][2] *= cr1[i]; oacc[i][j][3] *= cr1[i];
            }

#pragma unroll
        for (int ks = 0; ks < 4; ks++) {
            uint32_t o0 = (uint32_t)(((2 * ks) ^ g) << 4);
            uint32_t o1 = (uint32_t)(((2 * ks + 1) ^ g) << 4);
            uint32_t aH[2][4], bH[4][2];
#pragma unroll
            for (int i = 0; i < 2; i++) {
                uint32_t rh = SMB + SM_PH + pAoff[i];
                aH[i][0] = lds32(rh + o0); aH[i][1] = lds32(rh + 1024 + o0);
                aH[i][2] = lds32(rh + o1); aH[i][3] = lds32(rh + 1024 + o1);
            }
#pragma unroll
            for (int j = 0; j < 4; j++) {
                uint32_t rh = SMB + SM_VT + vBoff[j];
                bH[j][0] = lds32(rh + o0); bH[j][1] = lds32(rh + o1);
            }
#pragma unroll
            for (int i = 0; i < 2; i++)
#pragma unroll
                for (int j = 0; j < 4; j++)
                    mma_f16(oacc[i][j], aH[i], bH[j]);
        }
    }

    // --- epilogue: O / l -> fp16 att
#pragma unroll
    for (int i = 0; i < 2; i++) {
        int ra = wm * 32 + i * 16 + g;
        float la = 1.0f / l_s[ra];
        float lb = 1.0f / l_s[ra + 8];
        __half* oa = att + (size_t)(b * Sq + qtile * 64 + ra) * (NHq * Dh) + h * Dh;
        __half* ob = att + (size_t)(b * Sq + qtile * 64 + ra + 8) * (NHq * Dh) + h * Dh;
#pragma unroll
        for (int j = 0; j < 4; j++) {
            int cc = wn * 32 + j * 8 + 2 * q;
            __half2 va = __floats2half2_rn(oacc[i][j][0] * la, oacc[i][j][1] * la);
            __half2 vb = __floats2half2_rn(oacc[i][j][2] * lb, oacc[i][j][3] * lb);
            *(__half2*)(oa + cc) = va;
            *(__half2*)(ob + cc) = vb;
        }
    }
}

// ===========================================================================
extern "C" void kernel_launch(void* const* d_in, const int* in_sizes, int n_in,
                              void* d_out, int out_size) {
    const float* hs   = (const float*)d_in[0];
    const float* wqkv = (const float*)d_in[2];
    const float* wo   = (const float*)d_in[3];
    float* out = (float*)d_out;

    float* qkvp;
    __half *attp, *hsr, *wqkvT, *woT, *qhp, *qlp, *khp, *klp, *vthp;
    cudaGetSymbolAddress((void**)&qkvp, g_qkv);
    cudaGetSymbolAddress((void**)&attp, g_att);
    cudaGetSymbolAddress((void**)&hsr, g_hsr);
    cudaGetSymbolAddress((void**)&wqkvT, g_wqkvT);
    cudaGetSymbolAddress((void**)&woT, g_woT);
    cudaGetSymbolAddress((void**)&qhp, g_qh);
    cudaGetSymbolAddress((void**)&qlp, g_ql);
    cudaGetSymbolAddress((void**)&khp, g_kh);
    cudaGetSymbolAddress((void**)&klp, g_kl);
    cudaGetSymbolAddress((void**)&vthp, g_vth);

    const int GEMM_SMEM = NSTG * STAGE_BYTES;   // 96 KB
    cudaFuncSetAttribute((const void*)mma_gemm,
                         cudaFuncAttributeMaxDynamicSharedMemorySize, GEMM_SMEM);
    cudaFuncSetAttribute((const void*)attn_kernel,
                         cudaFuncAttributeMaxDynamicSharedMemorySize, ATTN_SMEM);

    // 0) operand prep for GEMM1
    transpose_half<<<dim3(QKVW / 32, H_DIM / 32), dim3(32, 8)>>>(wqkv, wqkvT, H_DIM, QKVW);
    transpose_half<<<dim3(H_DIM / 32, H_DIM / 32), dim3(32, 8)>>>(wo, woT, H_DIM, H_DIM);
    to_half_kernel<<<(Mrows * H_DIM / 4 + 255) / 256, 256>>>(hs, hsr, Mrows * H_DIM / 4);

    // 1) QKV GEMM
    mma_gemm<<<dim3(QKVW / 128, Mrows / 128), 256, GEMM_SMEM>>>(hsr, wqkvT, qkvp, QKVW);

    // 2+3) fused RoPE + split-fp16 operand prep
    prep_q<<<(Mrows * 1024 + 255) / 256, 256>>>(qkvp, qhp, qlp);
    prep_k<<<(Mrows * 256 + 255) / 256, 256>>>(qkvp, khp, klp);
    prep_vt<<<dim3(Dh / 32, Sq / 32, Bq * NKVq), dim3(32, 8)>>>(qkvp, vthp);

    // 4) attention (split-fp16 QK^T, single-fp16 PV, 2 CTAs/SM)
    attn_kernel<<<dim3(Sq / 64, Bq * NHq), 256, ATTN_SMEM>>>(qhp, qlp, khp, klp,
                                                             vthp, attp);

    // 5) output GEMM
    mma_gemm<<<dim3(H_DIM / 128, Mrows / 128), 256, GEMM_SMEM>>>(attp, woT, out, H_DIM);
}

// round 16
// speedup vs baseline: 1.7731x; 1.0725x over previous
#include <cuda_runtime.h>
#include <cuda_fp16.h>
#include <math.h>
#include <stdint.h>

#define H_DIM 4096
#define QKVW  6144          // (NH + 2*NKV) * D
#define NHq   32
#define NKVq  8
#define Dh    128
#define Sq    2048
#define Bq    2
#define Mrows 4096          // B * S
#define GK    4096          // K dim of both big GEMMs
#define NKCH  (GK / 64)     // 64 k-chunks per tile row

// GEMM pipeline: 3 stages x 32KB = 96KB -> 2 CTAs/SM
#define NSTG 3
#define STAGE_BYTES 32768
#define NIT  (GK / 64)

// attention smem layout (bytes) — single-buffered, 2 CTAs/SM
#define SM_QH 0            // 16KB
#define SM_QL 16384        // 16KB
#define SM_KH 32768        // 16KB
#define SM_KL 49152        // 16KB
#define SM_VT 65536        // 16KB
#define SM_PH 81920        // 8KB
#define SM_SS 90112        // fp32 scores 64 x 66 = 16896B
#define SM_MS 107008
#define SM_LS 107264
#define SM_CS 107520
#define ATTN_SMEM 107776

// scratch (device globals: allocation-guard compliant)
__device__ float  g_qkv[(size_t)Mrows * QKVW];
__device__ __half g_att[(size_t)Mrows * (NHq * Dh)];    // frag-order A tiles (GEMM2)
__device__ __half g_hsr[(size_t)Mrows * H_DIM];         // frag-order A tiles (GEMM1)
__device__ __half g_wqkvT[(size_t)QKVW * H_DIM];        // frag-order B tiles
__device__ __half g_woT[(size_t)H_DIM * H_DIM];         // frag-order B tiles
// attention operands (q,k hi/lo fp16 split; v fp16 only)
__device__ __half g_qh[(size_t)Mrows * (NHq * Dh)];
__device__ __half g_ql[(size_t)Mrows * (NHq * Dh)];
__device__ __half g_kh[(size_t)Mrows * (NKVq * Dh)];
__device__ __half g_kl[(size_t)Mrows * (NKVq * Dh)];
__device__ __half g_vth[(size_t)Mrows * (NKVq * Dh)];   // [b][kvh][d][s]

// ===========================================================================
// helpers (sm_80-era PTX only)
// ===========================================================================
__device__ __forceinline__ uint32_t smem_u32(const void* p) {
    uint32_t a;
    asm("{ .reg .u64 t; cvta.to.shared.u64 t, %1; cvt.u32.u64 %0, t; }" : "=r"(a) : "l"(p));
    return a;
}
__device__ __forceinline__ uint32_t lds32(uint32_t a) {
    uint32_t v; asm volatile("ld.shared.b32 %0, [%1];" : "=r"(v) : "r"(a)); return v;
}
__device__ __forceinline__ void lds64v(uint32_t* r, uint32_t a) {
    asm volatile("ld.shared.v2.b32 {%0,%1}, [%2];" : "=r"(r[0]), "=r"(r[1]) : "r"(a));
}
__device__ __forceinline__ void lds128v(uint32_t* r, uint32_t a) {
    asm volatile("ld.shared.v4.b32 {%0,%1,%2,%3}, [%4];"
                 : "=r"(r[0]), "=r"(r[1]), "=r"(r[2]), "=r"(r[3]) : "r"(a));
}
__device__ __forceinline__ void sts128(uint32_t a, uint4 v) {
    asm volatile("st.shared.v4.b32 [%0], {%1,%2,%3,%4};"
                 :: "r"(a), "r"(v.x), "r"(v.y), "r"(v.z), "r"(v.w) : "memory");
}
#define CP16(smaddr, gptr) \
    asm volatile("cp.async.cg.shared.global [%0], [%1], 16;" :: "r"(smaddr), "l"(gptr) : "memory")
#define CP_COMMIT() asm volatile("cp.async.commit_group;" ::: "memory")
#define CP_WAIT(n)  asm volatile("cp.async.wait_group %0;" :: "n"(n) : "memory")

// fp16 m16n8k16 MMA, fp32 accumulate
__device__ __forceinline__ void mma_f16(float* d, const uint32_t* a, const uint32_t* b) {
    asm volatile("mma.sync.aligned.m16n8k16.row.col.f32.f16.f16.f32 "
                 "{%0,%1,%2,%3}, {%4,%5,%6,%7}, {%8,%9}, {%0,%1,%2,%3};"
                 : "+f"(d[0]), "+f"(d[1]), "+f"(d[2]), "+f"(d[3])
                 : "r"(a[0]), "r"(a[1]), "r"(a[2]), "r"(a[3]), "r"(b[0]), "r"(b[1]));
}

// ===========================================================================
// Fragment-order tile layouts (R13-validated):
// A tile (128 rows x 64 halves = 16KB): lds128 at wm*8192 + ks*2048 + i*512
//   + lane*16 yields {a0,a1,a2,a3}.
// B tile (128 cols x 64 halves = 16KB): lds64 at wn*4096 + ks*1024 + j*256
//   + lane*8 yields {b0,b1}.
// ===========================================================================
__global__ __launch_bounds__(256, 2) void mma_gemm(const __half* __restrict__ A,
                                                   const __half* __restrict__ BT,
                                                   float* __restrict__ C, int Ntot) {
    extern __shared__ char smraw[];
    const uint32_t SB = smem_u32(smraw);

    int tid  = threadIdx.x;
    int lane = tid & 31, wid = tid >> 5;
    int wm = wid & 1, wn = wid >> 1;
    int g  = lane >> 2, q = lane & 3;

    // tile swizzle: groups of 8 N-tiles across all M-tiles (L2 locality)
    int l = blockIdx.y * gridDim.x + blockIdx.x;
    int per = gridDim.y << 3;
    int gq = l / per, rr = l - gq * per;
    int ntile = (gq << 3) + (rr & 7);
    int mtile = rr >> 3;

    const char* gaT = (const char*)A  + (size_t)mtile * NKCH * 16384;
    const char* gbT = (const char*)BT + (size_t)ntile * NKCH * 16384;

    float acc[4][4][4] = {};

#pragma unroll
    for (int p = 0; p < NSTG - 1; p++) {
        uint32_t as = SB + p * STAGE_BYTES;
#pragma unroll
        for (int cc = 0; cc < 4; cc++) {
            CP16(as + tid * 64 + cc * 16,         gaT + (size_t)p * 16384 + tid * 64 + cc * 16);
            CP16(as + 16384 + tid * 64 + cc * 16, gbT + (size_t)p * 16384 + tid * 64 + cc * 16);
        }
        CP_COMMIT();
    }

    uint32_t aBase = (uint32_t)(wm * 8192) + lane * 16;
    uint32_t bBase = 16384u + (uint32_t)(wn * 4096) + lane * 8;

    int scur = 0, spf = NSTG - 1;
    for (int it = 0; it < NIT; it++) {
        CP_WAIT(NSTG - 2);
        __syncthreads();

        int pf = it + NSTG - 1;
        if (pf < NIT) {
            uint32_t as = SB + spf * STAGE_BYTES;
#pragma unroll
            for (int cc = 0; cc < 4; cc++) {
                CP16(as + tid * 64 + cc * 16,         gaT + (size_t)pf * 16384 + tid * 64 + cc * 16);
                CP16(as + 16384 + tid * 64 + cc * 16, gbT + (size_t)pf * 16384 + tid * 64 + cc * 16);
            }
        }
        CP_COMMIT();

        uint32_t stage = SB + scur * STAGE_BYTES;
#pragma unroll
        for (int ks = 0; ks < 4; ks++) {
            uint32_t afr[4][4], bfr[4][2];
#pragma unroll
            for (int i = 0; i < 4; i++)
                lds128v(afr[i], stage + aBase + ks * 2048 + i * 512);
#pragma unroll
            for (int j = 0; j < 4; j++)
                lds64v(bfr[j], stage + bBase + ks * 1024 + j * 256);
#pragma unroll
            for (int i = 0; i < 4; i++)
#pragma unroll
                for (int j = 0; j < 4; j++)
                    mma_f16(acc[i][j], afr[i], bfr[j]);
        }

        if (++scur == NSTG) scur = 0;
        if (++spf == NSTG) spf = 0;
    }

    float* Cp = C + (size_t)(mtile * 128 + wm * 64 + g) * Ntot + ntile * 128 + wn * 32 + q * 2;
#pragma unroll
    for (int i = 0; i < 4; i++)
#pragma unroll
        for (int j = 0; j < 4; j++) {
            *(float2*)(Cp + (size_t)(i * 16) * Ntot + j * 8)     = make_float2(acc[i][j][0], acc[i][j][1]);
            *(float2*)(Cp + (size_t)(i * 16 + 8) * Ntot + j * 8) = make_float2(acc[i][j][2], acc[i][j][3]);
        }
}

// ===========================================================================
// prep: A operand (fp32 row-major) -> frag-order fp16 tiles (R13-validated)
// ===========================================================================
__global__ void prep_a_frag(const float* __restrict__ in, __half* __restrict__ out) {
    __shared__ uint32_t frag[4096];   // 16KB
    int kchunk = blockIdx.x, mtile = blockIdx.y;
    int tid = threadIdx.x;
    int r  = tid >> 1;
    int c0 = (tid & 1) * 16;

    const float* src = in + ((size_t)(mtile * 128 + r)) * GK + kchunk * 64 + c0 * 2;
    int wmHalf = r >> 6, gr = r & 63;
    uint32_t rowbase = (uint32_t)(wmHalf * 8192 + (gr >> 4) * 512 + ((gr >> 3) & 1) * 4
                                  + (gr & 7) * 64);
#pragma unroll
    for (int i4 = 0; i4 < 16; i4++) {
        float2 v = *(const float2*)(src + i4 * 2);
        __half2 hv = __floats2half2_rn(v.x, v.y);
        int c = c0 + i4;
        int w = c & 7, ks = c >> 3, qq = w & 3, hi = w >> 2;
        frag[(rowbase + ks * 2048 + qq * 16 + hi * 8) >> 2] = *(uint32_t*)&hv;
    }
    __syncthreads();
    uint4* dst = (uint4*)(out + ((size_t)(mtile * NKCH + kchunk)) * 8192);
    const uint4* s4 = (const uint4*)frag;
#pragma unroll
    for (int i = 0; i < 4; i++) dst[tid + i * 256] = s4[tid + i * 256];
}

// ===========================================================================
// prep: B operand (fp32 [K][N] row-major) -> frag-order fp16 tiles (R13-validated)
// ===========================================================================
__global__ void prep_b_frag(const float* __restrict__ in, __half* __restrict__ out, int N) {
    __shared__ __half t[64][136];
    __shared__ uint32_t frag[4096];
    int kchunk = blockIdx.x, ntile = blockIdx.y;
    int tid = threadIdx.x;
    int k0 = kchunk * 64, n0 = ntile * 128;

    {
        int nn = (tid & 31) * 4;
        int kk0 = tid >> 5;
#pragma unroll
        for (int kk = 0; kk < 64; kk += 8) {
            float4 v = *(const float4*)(in + (size_t)(k0 + kk + kk0) * N + n0 + nn);
            t[kk + kk0][nn]     = __float2half_rn(v.x);
            t[kk + kk0][nn + 1] = __float2half_rn(v.y);
            t[kk + kk0][nn + 2] = __float2half_rn(v.z);
            t[kk + kk0][nn + 3] = __float2half_rn(v.w);
        }
    }
    __syncthreads();
    {
        int col = tid >> 1;
        int c0  = (tid & 1) * 16;
        uint32_t colbase = (uint32_t)((col >> 5) * 4096 + ((col >> 3) & 3) * 256
                                      + (col & 7) * 32);
#pragma unroll
        for (int i = 0; i < 16; i++) {
            int c = c0 + i;
            int w = c & 7, ks = c >> 3, qq = w & 3, hi = w >> 2;
            __half2 hv = __halves2half2(t[c * 2][col], t[c * 2 + 1][col]);
            frag[(colbase + ks * 1024 + qq * 8 + hi * 4) >> 2] = *(uint32_t*)&hv;
        }
    }
    __syncthreads();
    uint4* dst = (uint4*)(out + ((size_t)(ntile * NKCH + kchunk)) * 8192);
    const uint4* s4 = (const uint4*)frag;
#pragma unroll
    for (int i = 0; i < 4; i++) dst[tid + i * 256] = s4[tid + i * 256];
}

// ===========================================================================
// fused RoPE + q/k split, v transpose (R15-proven)
// ===========================================================================
__global__ void prep_q(const float* __restrict__ qkv,
                       __half* __restrict__ qh, __half* __restrict__ ql) {
    const float scale = 0.08838834764831845f;
    int t = blockIdx.x * blockDim.x + threadIdx.x;
    if (t >= Mrows * (NHq * Dh / 4)) return;
    int m = t / 1024;
    int cc = (t % 1024) * 4;
    int h = cc >> 7, d = cc & 127;
    int b = m >> 11, s = m & 2047;
    float4 v = *(const float4*)(qkv + (size_t)m * QKVW + cc);
    float f[4];
    {
        int p0 = d >> 1;
        float i0 = exp2f(-(float)p0 * (13.287712379549449f / 64.0f));
        float i1 = exp2f(-(float)(p0 + 1) * (13.287712379549449f / 64.0f));
        float sn0, cs0, sn1, cs1;
        sincosf((float)s * i0, &sn0, &cs0);
        sincosf((float)s * i1, &sn1, &cs1);
        f[0] = (v.x * cs0 - v.y * sn0) * scale;
        f[1] = (v.y * cs0 + v.x * sn0) * scale;
        f[2] = (v.z * cs1 - v.w * sn1) * scale;
        f[3] = (v.w * cs1 + v.z * sn1) * scale;
    }
    size_t o = ((size_t)((b * NHq + h) * Sq + s)) * Dh + d;
    __half hh[4], hl[4];
#pragma unroll
    for (int i = 0; i < 4; i++) {
        hh[i] = __float2half_rn(f[i]);
        hl[i] = __float2half_rn(f[i] - __half2float(hh[i]));
    }
    *(uint2*)(qh + o) = *(uint2*)hh;
    *(uint2*)(ql + o) = *(uint2*)hl;
}

__global__ void prep_k(const float* __restrict__ qkv,
                       __half* __restrict__ kh, __half* __restrict__ kl) {
    int t = blockIdx.x * blockDim.x + threadIdx.x;
    if (t >= Mrows * (NKVq * Dh / 4)) return;
    int m = t / 256;
    int cc = (t % 256) * 4;
    int kvh = cc >> 7, d = cc & 127;
    int b = m >> 11, s = m & 2047;
    float4 v = *(const float4*)(qkv + (size_t)m * QKVW + NHq * Dh + cc);
    float f[4];
    {
        int p0 = d >> 1;
        float i0 = exp2f(-(float)p0 * (13.287712379549449f / 64.0f));
        float i1 = exp2f(-(float)(p0 + 1) * (13.287712379549449f / 64.0f));
        float sn0, cs0, sn1, cs1;
        sincosf((float)s * i0, &sn0, &cs0);
        sincosf((float)s * i1, &sn1, &cs1);
        f[0] = v.x * cs0 - v.y * sn0;
        f[1] = v.y * cs0 + v.x * sn0;
        f[2] = v.z * cs1 - v.w * sn1;
        f[3] = v.w * cs1 + v.z * sn1;
    }
    size_t o = ((size_t)((b * NKVq + kvh) * Sq + s)) * Dh + d;
    __half hh[4], hl[4];
#pragma unroll
    for (int i = 0; i < 4; i++) {
        hh[i] = __float2half_rn(f[i]);
        hl[i] = __float2half_rn(f[i] - __half2float(hh[i]));
    }
    *(uint2*)(kh + o) = *(uint2*)hh;
    *(uint2*)(kl + o) = *(uint2*)hl;
}

__global__ void prep_vt(const float* __restrict__ qkv, __half* __restrict__ vth) {
    __shared__ float t[32][33];
    int bk = blockIdx.z;
    int b = bk >> 3, kvh = bk & 7;
    int x = blockIdx.x * 32 + threadIdx.x;   // d
    int y0 = blockIdx.y * 32;                // s
    const float* src = qkv + (size_t)(b * Sq) * QKVW + (NHq + NKVq) * Dh + kvh * Dh;
#pragma unroll
    for (int j = threadIdx.y; j < 32; j += 8)
        t[j][threadIdx.x] = src[(size_t)(y0 + j) * QKVW + x];
    __syncthreads();
    int xo = y0 + threadIdx.x;      // s
    int yo0 = blockIdx.x * 32;      // d
#pragma unroll
    for (int j = threadIdx.y; j < 32; j += 8) {
        float v = t[threadIdx.x][j];
        int d = yo0 + j;
        vth[((size_t)bk * Dh + d) * Sq + xo] = __float2half_rn(v);
    }
}

// ===========================================================================
// Causal GQA flash attention: split-fp16 QK^T, single-fp16 PV, 2 CTAs/SM,
// split prefetch (K after softmax, V after PV) overlaps loads with compute.
// Epilogue writes att in frag-order A tiles for GEMM2 (R13-validated).
// ===========================================================================
__global__ __launch_bounds__(256, 2) void attn_kernel(const __half* __restrict__ qh,
                                                      const __half* __restrict__ ql,
                                                      const __half* __restrict__ kh,
                                                      const __half* __restrict__ kl,
                                                      const __half* __restrict__ vth,
                                                      __half* __restrict__ att) {
    extern __shared__ char smc[];
    const uint32_t SMB = smem_u32(smc);
    float* Ss  = (float*)(smc + SM_SS);
    float* m_s = (float*)(smc + SM_MS);
    float* l_s = (float*)(smc + SM_LS);
    float* c_s = (float*)(smc + SM_CS);

    int tid  = threadIdx.x;
    int lane = tid & 31, wid = tid >> 5;
    int g = lane >> 2, q = lane & 3;
    int wm = wid & 1, wn = wid >> 1;

    int qtile = blockIdx.x;
    int bh    = blockIdx.y;
    int b     = bh >> 5;
    int h     = bh & 31;
    int kvh   = h >> 2;

    const __half* qhb = qh + ((size_t)((b * NHq + h) * Sq + qtile * 64)) * Dh;
    const __half* qlb = ql + ((size_t)((b * NHq + h) * Sq + qtile * 64)) * Dh;
    const __half* khb = kh + ((size_t)((b * NKVq + kvh) * Sq)) * Dh;
    const __half* klb = kl + ((size_t)((b * NKVq + kvh) * Sq)) * Dh;
    const __half* vthb = vth + ((size_t)(b * NKVq + kvh) * Dh) * Sq;

    int krow = tid >> 2, kc0 = (tid & 3) * 4;
    int vrow = tid >> 1, vc0 = (tid & 1) * 4;

    // --- prologue: load Q + K[0] + V[0]
    {
#pragma unroll
        for (int cc = 0; cc < 4; cc++) {
            int c = kc0 + cc;
            int kc = c >> 3;
            uint32_t so = (uint32_t)(((c & 7) ^ (krow & 7)) << 4);
            uint32_t dst = SMB + kc * 8192 + krow * 128 + so;
            CP16(dst + SM_QH, (const char*)(qhb + (size_t)krow * Dh + c * 8));
            CP16(dst + SM_QL, (const char*)(qlb + (size_t)krow * Dh + c * 8));
        }
        const __half* kph = khb + (size_t)krow * Dh;
        const __half* kpl = klb + (size_t)krow * Dh;
#pragma unroll
        for (int cc = 0; cc < 4; cc++) {
            int c = kc0 + cc;
            int kc = c >> 3;
            uint32_t so = (uint32_t)(((c & 7) ^ (krow & 7)) << 4);
            uint32_t dst = SMB + SM_KH + kc * 8192 + krow * 128 + so;
            CP16(dst, (const char*)(kph + c * 8));
            CP16(dst + 16384, (const char*)(kpl + c * 8));
        }
        const __half* vph = vthb + (size_t)vrow * Sq;
#pragma unroll
        for (int cc = 0; cc < 4; cc++) {
            int c = vc0 + cc;
            uint32_t so = (uint32_t)((c ^ (vrow & 7)) << 4);
            CP16(SMB + SM_VT + vrow * 128 + so, (const char*)(vph + c * 8));
        }
        CP_COMMIT();
    }
    if (tid < 64) { m_s[tid] = -1e30f; l_s[tid] = 0.0f; }

    int srow = tid >> 2, ssub = tid & 3;

    uint32_t qAoff[2], kBoff[2], pAoff[2], vBoff[4];
#pragma unroll
    for (int i = 0; i < 2; i++) {
        qAoff[i] = (uint32_t)((wm * 32 + i * 16 + g) * 128 + q * 4);
        pAoff[i] = qAoff[i];
    }
#pragma unroll
    for (int j = 0; j < 2; j++)
        kBoff[j] = (uint32_t)((wn * 16 + j * 8 + g) * 128 + q * 4);
#pragma unroll
    for (int j = 0; j < 4; j++)
        vBoff[j] = (uint32_t)((wn * 32 + j * 8 + g) * 128 + q * 4);

    float oacc[2][4][4] = {};

    for (int kt = 0; kt <= qtile; kt++) {
        CP_WAIT(0);
        __syncthreads();

        // --- QK^T: split fp16 MMA (Qh*Kh + Qh*Kl + Ql*Kh)
        float sacc[2][2][4] = {};
#pragma unroll
        for (int kc = 0; kc < 2; kc++) {
            uint32_t qbh = SMB + SM_QH + kc * 8192, qbl = SMB + SM_QL + kc * 8192;
            uint32_t kbh = SMB + SM_KH + kc * 8192, kbl = SMB + SM_KL + kc * 8192;
#pragma unroll
            for (int ks = 0; ks < 4; ks++) {
                uint32_t o0 = (uint32_t)(((2 * ks) ^ g) << 4);
                uint32_t o1 = (uint32_t)(((2 * ks + 1) ^ g) << 4);
                uint32_t aH[2][4], aL[2][4], bH[2][2], bL[2][2];
#pragma unroll
                for (int i = 0; i < 2; i++) {
                    uint32_t rh = qbh + qAoff[i], rl2 = qbl + qAoff[i];
                    aH[i][0] = lds32(rh + o0); aH[i][1] = lds32(rh + 1024 + o0);
                    aH[i][2] = lds32(rh + o1); aH[i][3] = lds32(rh + 1024 + o1);
                    aL[i][0] = lds32(rl2 + o0); aL[i][1] = lds32(rl2 + 1024 + o0);
                    aL[i][2] = lds32(rl2 + o1); aL[i][3] = lds32(rl2 + 1024 + o1);
                }
#pragma unroll
                for (int j = 0; j < 2; j++) {
                    uint32_t rh = kbh + kBoff[j], rl2 = kbl + kBoff[j];
                    bH[j][0] = lds32(rh + o0); bH[j][1] = lds32(rh + o1);
                    bL[j][0] = lds32(rl2 + o0); bL[j][1] = lds32(rl2 + o1);
                }
#pragma unroll
                for (int i = 0; i < 2; i++)
#pragma unroll
                    for (int j = 0; j < 2; j++) {
                        mma_f16(sacc[i][j], aH[i], bH[j]);
                        mma_f16(sacc[i][j], aH[i], bL[j]);
                        mma_f16(sacc[i][j], aL[i], bH[j]);
                    }
            }
        }
#pragma unroll
        for (int i = 0; i < 2; i++)
#pragma unroll
            for (int j = 0; j < 2; j++) {
                int r0 = wm * 32 + i * 16 + g;
                int cc = wn * 16 + j * 8 + 2 * q;
                *(float2*)&Ss[r0 * 66 + cc]       = make_float2(sacc[i][j][0], sacc[i][j][1]);
                *(float2*)&Ss[(r0 + 8) * 66 + cc] = make_float2(sacc[i][j][2], sacc[i][j][3]);
            }
        __syncthreads();

        // --- online softmax (4 threads/row), write P fp16
        {
            int limit = (kt == qtile) ? srow : 63;
            float tm = -1e30f;
            float pv_[16];
#pragma unroll
            for (int j = 0; j < 16; j++) {
                int c = ssub * 16 + j;
                float v = Ss[srow * 66 + c];
                if (c <= limit) tm = fmaxf(tm, v);
            }
            tm = fmaxf(tm, __shfl_xor_sync(0xFFFFFFFFu, tm, 1));
            tm = fmaxf(tm, __shfl_xor_sync(0xFFFFFFFFu, tm, 2));
            float mold = m_s[srow];
            float mnew = fmaxf(mold, tm);
            float sum = 0.0f;
#pragma unroll
            for (int j = 0; j < 16; j++) {
                int c = ssub * 16 + j;
                float p = (c <= limit) ? __expf(Ss[srow * 66 + c] - mnew) : 0.0f;
                pv_[j] = p;
                sum += p;
            }
#pragma unroll
            for (int c2 = 0; c2 < 2; c2++) {
                int c = ssub * 2 + c2;
                uint32_t hw[4];
#pragma unroll
                for (int t2 = 0; t2 < 4; t2++) {
                    __half2 hh = __floats2half2_rn(pv_[c2 * 8 + 2 * t2], pv_[c2 * 8 + 2 * t2 + 1]);
                    hw[t2] = *(uint32_t*)&hh;
                }
                uint32_t so = (uint32_t)((c ^ (srow & 7)) << 4);
                sts128(SMB + SM_PH + srow * 128 + so, make_uint4(hw[0], hw[1], hw[2], hw[3]));
            }
            sum += __shfl_xor_sync(0xFFFFFFFFu, sum, 1);
            sum += __shfl_xor_sync(0xFFFFFFFFu, sum, 2);
            if (ssub == 0) {
                float corr = __expf(mold - mnew);
                l_s[srow] = l_s[srow] * corr + sum;
                m_s[srow] = mnew;
                c_s[srow] = corr;
            }
        }
        __syncthreads();

        // K buffer is dead now: prefetch K[kt+1] under PV compute
        if (kt < qtile) {
            const __half* kph = khb + (size_t)((kt + 1) * 64 + krow) * Dh;
            const __half* kpl = klb + (size_t)((kt + 1) * 64 + krow) * Dh;
#pragma unroll
            for (int cc = 0; cc < 4; cc++) {
                int c = kc0 + cc;
                int kc = c >> 3;
                uint32_t so = (uint32_t)(((c & 7) ^ (krow & 7)) << 4);
                uint32_t dst = SMB + SM_KH + kc * 8192 + krow * 128 + so;
                CP16(dst, (const char*)(kph + c * 8));
                CP16(dst + 16384, (const char*)(kpl + c * 8));
            }
            CP_COMMIT();
        }

        // --- O rescale, then O += P @ VT (single fp16 MMA)
        float cr0[2], cr1[2];
#pragma unroll
        for (int i = 0; i < 2; i++) {
            cr0[i] = c_s[wm * 32 + i * 16 + g];
            cr1[i] = c_s[wm * 32 + i * 16 + 8 + g];
        }
#pragma unroll
        for (int i = 0; i < 2; i++)
#pragma unroll
            for (int j = 0; j < 4; j++) {
                oacc[i][j][0] *= cr0[i]; oacc[i][j][1] *= cr0[i];
                oacc[i][j][2] *= cr1[i]; oacc[i][j][3] *= cr1[i];
            }

#pragma unroll
        for (int ks = 0; ks < 4; ks++) {
            uint32_t o0 = (uint32_t)(((2 * ks) ^ g) << 4);
            uint32_t o1 = (uint32_t)(((2 * ks + 1) ^ g) << 4);
            uint32_t aH[2][4], bH[4][2];
#pragma unroll
            for (int i = 0; i < 2; i++) {
                uint32_t rh = SMB + SM_PH + pAoff[i];
                aH[i][0] = lds32(rh + o0); aH[i][1] = lds32(rh + 1024 + o0);
                aH[i][2] = lds32(rh + o1); aH[i][3] = lds32(rh + 1024 + o1);
            }
#pragma unroll
            for (int j = 0; j < 4; j++) {
                uint32_t rh = SMB + SM_VT + vBoff[j];
                bH[j][0] = lds32(rh + o0); bH[j][1] = lds32(rh + o1);
            }
#pragma unroll
            for (int i = 0; i < 2; i++)
#pragma unroll
                for (int j = 0; j < 4; j++)
                    mma_f16(oacc[i][j], aH[i], bH[j]);
        }
        __syncthreads();   // all VT reads done

        // V buffer is dead now: prefetch V[kt+1]
        if (kt < qtile) {
            const __half* vph = vthb + (size_t)vrow * Sq + (kt + 1) * 64;
#pragma unroll
            for (int cc = 0; cc < 4; cc++) {
                int c = vc0 + cc;
                uint32_t so = (uint32_t)((c ^ (vrow & 7)) << 4);
                CP16(SMB + SM_VT + vrow * 128 + so, (const char*)(vph + c * 8));
            }
            CP_COMMIT();
        }
    }

    // --- epilogue: O / l -> frag-order A tiles for GEMM2 (R13-validated)
    {
        int mtileA = (b * Sq + qtile * 64) >> 7;
        uint32_t wmHalf = (uint32_t)(qtile & 1) * 8192;
#pragma unroll
        for (int i = 0; i < 2; i++) {
            int ra = wm * 32 + i * 16 + g;
            float la = 1.0f / l_s[ra];
            float lb = 1.0f / l_s[ra + 8];
            uint32_t iblk = (uint32_t)(wm * 2 + i) * 512;
#pragma unroll
            for (int j = 0; j < 4; j++) {
                int kchunk = 2 * h + (wn >> 1);
                int ks = (wn & 1) * 2 + (j >> 1);
                __half2 va = __floats2half2_rn(oacc[i][j][0] * la, oacc[i][j][1] * la);
                __half2 vb = __floats2half2_rn(oacc[i][j][2] * lb, oacc[i][j][3] * lb);
                char* base = (char*)att + ((size_t)mtileA * NKCH + kchunk) * 16384
                             + wmHalf + ks * 2048 + iblk + (g * 4 + q) * 16 + (j & 1) * 8;
                *(uint2*)base = make_uint2(*(uint32_t*)&va, *(uint32_t*)&vb);
            }
        }
    }
}

// ===========================================================================
extern "C" void kernel_launch(void* const* d_in, const int* in_sizes, int n_in,
                              void* d_out, int out_size) {
    const float* hs   = (const float*)d_in[0];
    const float* wqkv = (const float*)d_in[2];
    const float* wo   = (const float*)d_in[3];
    float* out = (float*)d_out;

    float* qkvp;
    __half *attp, *hsr, *wqkvT, *woT, *qhp, *qlp, *khp, *klp, *vthp;
    cudaGetSymbolAddress((void**)&qkvp, g_qkv);
    cudaGetSymbolAddress((void**)&attp, g_att);
    cudaGetSymbolAddress((void**)&hsr, g_hsr);
    cudaGetSymbolAddress((void**)&wqkvT, g_wqkvT);
    cudaGetSymbolAddress((void**)&woT, g_woT);
    cudaGetSymbolAddress((void**)&qhp, g_qh);
    cudaGetSymbolAddress((void**)&qlp, g_ql);
    cudaGetSymbolAddress((void**)&khp, g_kh);
    cudaGetSymbolAddress((void**)&klp, g_kl);
    cudaGetSymbolAddress((void**)&vthp, g_vth);

    const int GEMM_SMEM = NSTG * STAGE_BYTES;   // 96 KB
    cudaFuncSetAttribute((const void*)mma_gemm,
                         cudaFuncAttributeMaxDynamicSharedMemorySize, GEMM_SMEM);
    cudaFuncSetAttribute((const void*)attn_kernel,
                         cudaFuncAttributeMaxDynamicSharedMemorySize, ATTN_SMEM);

    // 0) operand prep: frag-order tiles
    prep_a_frag<<<dim3(NKCH, Mrows / 128), 256>>>(hs, hsr);
    prep_b_frag<<<dim3(NKCH, QKVW / 128), 256>>>(wqkv, wqkvT, QKVW);
    prep_b_frag<<<dim3(NKCH, H_DIM / 128), 256>>>(wo, woT, H_DIM);

    // 1) QKV GEMM
    mma_gemm<<<dim3(QKVW / 128, Mrows / 128), 256, GEMM_SMEM>>>(hsr, wqkvT, qkvp, QKVW);

    // 2+3) fused RoPE + split-fp16 operand prep
    prep_q<<<(Mrows * 1024 + 255) / 256, 256>>>(qkvp, qhp, qlp);
    prep_k<<<(Mrows * 256 + 255) / 256, 256>>>(qkvp, khp, klp);
    prep_vt<<<dim3(Dh / 32, Sq / 32, Bq * NKVq), dim3(32, 8)>>>(qkvp, vthp);

    // 4) attention (split-fp16 QK^T, single-fp16 PV, 2 CTAs/SM, split prefetch)
    attn_kernel<<<dim3(Sq / 64, Bq * NHq), 256, ATTN_SMEM>>>(qhp, qlp, khp, klp,
                                                             vthp, attp);

    // 5) output GEMM
    mma_gemm<<<dim3(H_DIM / 128, Mrows / 128), 256, GEMM_SMEM>>>(attp, woT, out, H_DIM);
}

// round 17
// speedup vs baseline: 1.7764x; 1.0019x over previous
#include <cuda_runtime.h>
#include <cuda_fp16.h>
#include <math.h>
#include <stdint.h>

#define H_DIM 4096
#define QKVW  6144          // (NH + 2*NKV) * D
#define NHq   32
#define NKVq  8
#define Dh    128
#define Sq    2048
#define Bq    2
#define Mrows 4096          // B * S
#define GK    4096          // K dim of both big GEMMs
#define NKCH  (GK / 64)     // 64 k-chunks per tile row

// GEMM pipeline: 3 stages x 32KB = 96KB -> 2 CTAs/SM
#define NSTG 3
#define STAGE_BYTES 32768
#define NIT  (GK / 64)

// attention smem layout (bytes) — single-buffered, 2 CTAs/SM
#define SM_QH 0            // 16KB
#define SM_QL 16384        // 16KB
#define SM_KH 32768        // 16KB
#define SM_KL 49152        // 16KB
#define SM_VT 65536        // 16KB
#define SM_PH 81920        // 8KB
#define SM_SS 90112        // fp32 scores 64 x 66 = 16896B
#define SM_MS 107008
#define SM_LS 107264
#define SM_CS 107520
#define ATTN_SMEM 107776

// scratch (device globals: allocation-guard compliant)
__device__ float  g_qkv[(size_t)Mrows * QKVW];
__device__ __half g_att[(size_t)Mrows * (NHq * Dh)];    // frag-order A tiles (GEMM2)
__device__ __half g_hsr[(size_t)Mrows * H_DIM];         // frag-order A tiles (GEMM1)
__device__ __half g_wqkvT[(size_t)QKVW * H_DIM];        // frag-order B tiles
__device__ __half g_woT[(size_t)H_DIM * H_DIM];         // frag-order B tiles
// attention operands (q,k hi/lo fp16 split; v fp16 only)
__device__ __half g_qh[(size_t)Mrows * (NHq * Dh)];
__device__ __half g_ql[(size_t)Mrows * (NHq * Dh)];
__device__ __half g_kh[(size_t)Mrows * (NKVq * Dh)];
__device__ __half g_kl[(size_t)Mrows * (NKVq * Dh)];
__device__ __half g_vth[(size_t)Mrows * (NKVq * Dh)];   // [b][kvh][d][s]
// rope table: (cos, sin) per (s, pair)
__device__ float2 g_rope[(size_t)Sq * 64];

// ===========================================================================
// helpers (sm_80-era PTX only)
// ===========================================================================
__device__ __forceinline__ uint32_t smem_u32(const void* p) {
    uint32_t a;
    asm("{ .reg .u64 t; cvta.to.shared.u64 t, %1; cvt.u32.u64 %0, t; }" : "=r"(a) : "l"(p));
    return a;
}
__device__ __forceinline__ uint32_t lds32(uint32_t a) {
    uint32_t v; asm volatile("ld.shared.b32 %0, [%1];" : "=r"(v) : "r"(a)); return v;
}
__device__ __forceinline__ void lds64v(uint32_t* r, uint32_t a) {
    asm volatile("ld.shared.v2.b32 {%0,%1}, [%2];" : "=r"(r[0]), "=r"(r[1]) : "r"(a));
}
__device__ __forceinline__ void lds128v(uint32_t* r, uint32_t a) {
    asm volatile("ld.shared.v4.b32 {%0,%1,%2,%3}, [%4];"
                 : "=r"(r[0]), "=r"(r[1]), "=r"(r[2]), "=r"(r[3]) : "r"(a));
}
__device__ __forceinline__ void sts128(uint32_t a, uint4 v) {
    asm volatile("st.shared.v4.b32 [%0], {%1,%2,%3,%4};"
                 :: "r"(a), "r"(v.x), "r"(v.y), "r"(v.z), "r"(v.w) : "memory");
}
#define CP16(smaddr, gptr) \
    asm volatile("cp.async.cg.shared.global [%0], [%1], 16;" :: "r"(smaddr), "l"(gptr) : "memory")
#define CP_COMMIT() asm volatile("cp.async.commit_group;" ::: "memory")
#define CP_WAIT(n)  asm volatile("cp.async.wait_group %0;" :: "n"(n) : "memory")

// fp16 m16n8k16 MMA, fp32 accumulate
__device__ __forceinline__ void mma_f16(float* d, const uint32_t* a, const uint32_t* b) {
    asm volatile("mma.sync.aligned.m16n8k16.row.col.f32.f16.f16.f32 "
                 "{%0,%1,%2,%3}, {%4,%5,%6,%7}, {%8,%9}, {%0,%1,%2,%3};"
                 : "+f"(d[0]), "+f"(d[1]), "+f"(d[2]), "+f"(d[3])
                 : "r"(a[0]), "r"(a[1]), "r"(a[2]), "r"(a[3]), "r"(b[0]), "r"(b[1]));
}

// ===========================================================================
// fp16 mma.sync GEMM, frag-order operands (R16-proven)
// ===========================================================================
__global__ __launch_bounds__(256, 2) void mma_gemm(const __half* __restrict__ A,
                                                   const __half* __restrict__ BT,
                                                   float* __restrict__ C, int Ntot) {
    extern __shared__ char smraw[];
    const uint32_t SB = smem_u32(smraw);

    int tid  = threadIdx.x;
    int lane = tid & 31, wid = tid >> 5;
    int wm = wid & 1, wn = wid >> 1;
    int g  = lane >> 2, q = lane & 3;

    int l = blockIdx.y * gridDim.x + blockIdx.x;
    int per = gridDim.y << 3;
    int gq = l / per, rr = l - gq * per;
    int ntile = (gq << 3) + (rr & 7);
    int mtile = rr >> 3;

    const char* gaT = (const char*)A  + (size_t)mtile * NKCH * 16384;
    const char* gbT = (const char*)BT + (size_t)ntile * NKCH * 16384;

    float acc[4][4][4] = {};

#pragma unroll
    for (int p = 0; p < NSTG - 1; p++) {
        uint32_t as = SB + p * STAGE_BYTES;
#pragma unroll
        for (int cc = 0; cc < 4; cc++) {
            CP16(as + tid * 64 + cc * 16,         gaT + (size_t)p * 16384 + tid * 64 + cc * 16);
            CP16(as + 16384 + tid * 64 + cc * 16, gbT + (size_t)p * 16384 + tid * 64 + cc * 16);
        }
        CP_COMMIT();
    }

    uint32_t aBase = (uint32_t)(wm * 8192) + lane * 16;
    uint32_t bBase = 16384u + (uint32_t)(wn * 4096) + lane * 8;

    int scur = 0, spf = NSTG - 1;
    for (int it = 0; it < NIT; it++) {
        CP_WAIT(NSTG - 2);
        __syncthreads();

        int pf = it + NSTG - 1;
        if (pf < NIT) {
            uint32_t as = SB + spf * STAGE_BYTES;
#pragma unroll
            for (int cc = 0; cc < 4; cc++) {
                CP16(as + tid * 64 + cc * 16,         gaT + (size_t)pf * 16384 + tid * 64 + cc * 16);
                CP16(as + 16384 + tid * 64 + cc * 16, gbT + (size_t)pf * 16384 + tid * 64 + cc * 16);
            }
        }
        CP_COMMIT();

        uint32_t stage = SB + scur * STAGE_BYTES;
#pragma unroll
        for (int ks = 0; ks < 4; ks++) {
            uint32_t afr[4][4], bfr[4][2];
#pragma unroll
            for (int i = 0; i < 4; i++)
                lds128v(afr[i], stage + aBase + ks * 2048 + i * 512);
#pragma unroll
            for (int j = 0; j < 4; j++)
                lds64v(bfr[j], stage + bBase + ks * 1024 + j * 256);
#pragma unroll
            for (int i = 0; i < 4; i++)
#pragma unroll
                for (int j = 0; j < 4; j++)
                    mma_f16(acc[i][j], afr[i], bfr[j]);
        }

        if (++scur == NSTG) scur = 0;
        if (++spf == NSTG) spf = 0;
    }

    float* Cp = C + (size_t)(mtile * 128 + wm * 64 + g) * Ntot + ntile * 128 + wn * 32 + q * 2;
#pragma unroll
    for (int i = 0; i < 4; i++)
#pragma unroll
        for (int j = 0; j < 4; j++) {
            *(float2*)(Cp + (size_t)(i * 16) * Ntot + j * 8)     = make_float2(acc[i][j][0], acc[i][j][1]);
            *(float2*)(Cp + (size_t)(i * 16 + 8) * Ntot + j * 8) = make_float2(acc[i][j][2], acc[i][j][3]);
        }
}

// ===========================================================================
// prep: A/B operands -> frag-order fp16 tiles (R13/R16-validated)
// ===========================================================================
__global__ void prep_a_frag(const float* __restrict__ in, __half* __restrict__ out) {
    __shared__ uint32_t frag[4096];
    int kchunk = blockIdx.x, mtile = blockIdx.y;
    int tid = threadIdx.x;
    int r  = tid >> 1;
    int c0 = (tid & 1) * 16;

    const float* src = in + ((size_t)(mtile * 128 + r)) * GK + kchunk * 64 + c0 * 2;
    int wmHalf = r >> 6, gr = r & 63;
    uint32_t rowbase = (uint32_t)(wmHalf * 8192 + (gr >> 4) * 512 + ((gr >> 3) & 1) * 4
                                  + (gr & 7) * 64);
#pragma unroll
    for (int i4 = 0; i4 < 16; i4++) {
        float2 v = *(const float2*)(src + i4 * 2);
        __half2 hv = __floats2half2_rn(v.x, v.y);
        int c = c0 + i4;
        int w = c & 7, ks = c >> 3, qq = w & 3, hi = w >> 2;
        frag[(rowbase + ks * 2048 + qq * 16 + hi * 8) >> 2] = *(uint32_t*)&hv;
    }
    __syncthreads();
    uint4* dst = (uint4*)(out + ((size_t)(mtile * NKCH + kchunk)) * 8192);
    const uint4* s4 = (const uint4*)frag;
#pragma unroll
    for (int i = 0; i < 4; i++) dst[tid + i * 256] = s4[tid + i * 256];
}

__global__ void prep_b_frag(const float* __restrict__ in, __half* __restrict__ out, int N) {
    __shared__ __half t[64][136];
    __shared__ uint32_t frag[4096];
    int kchunk = blockIdx.x, ntile = blockIdx.y;
    int tid = threadIdx.x;
    int k0 = kchunk * 64, n0 = ntile * 128;

    {
        int nn = (tid & 31) * 4;
        int kk0 = tid >> 5;
#pragma unroll
        for (int kk = 0; kk < 64; kk += 8) {
            float4 v = *(const float4*)(in + (size_t)(k0 + kk + kk0) * N + n0 + nn);
            t[kk + kk0][nn]     = __float2half_rn(v.x);
            t[kk + kk0][nn + 1] = __float2half_rn(v.y);
            t[kk + kk0][nn + 2] = __float2half_rn(v.z);
            t[kk + kk0][nn + 3] = __float2half_rn(v.w);
        }
    }
    __syncthreads();
    {
        int col = tid >> 1;
        int c0  = (tid & 1) * 16;
        uint32_t colbase = (uint32_t)((col >> 5) * 4096 + ((col >> 3) & 3) * 256
                                      + (col & 7) * 32);
#pragma unroll
        for (int i = 0; i < 16; i++) {
            int c = c0 + i;
            int w = c & 7, ks = c >> 3, qq = w & 3, hi = w >> 2;
            __half2 hv = __halves2half2(t[c * 2][col], t[c * 2 + 1][col]);
            frag[(colbase + ks * 1024 + qq * 8 + hi * 4) >> 2] = *(uint32_t*)&hv;
        }
    }
    __syncthreads();
    uint4* dst = (uint4*)(out + ((size_t)(ntile * NKCH + kchunk)) * 8192);
    const uint4* s4 = (const uint4*)frag;
#pragma unroll
    for (int i = 0; i < 4; i++) dst[tid + i * 256] = s4[tid + i * 256];
}

// ===========================================================================
// rope table: g_rope[s][p] = (cos(s*inv_p), sin(s*inv_p))
// ===========================================================================
__global__ void rope_table(float2* __restrict__ tab) {
    int t = blockIdx.x * blockDim.x + threadIdx.x;
    if (t >= Sq * 64) return;
    int s = t >> 6, p = t & 63;
    float inv = exp2f(-(float)p * (13.287712379549449f / 64.0f));
    float sn, cs;
    sincosf((float)s * inv, &sn, &cs);
    tab[t] = make_float2(cs, sn);
}

// fused RoPE (table) + q split: -> [b][h][s][d] hi/lo, pre-scaled 1/sqrt(D)
__global__ void prep_q(const float* __restrict__ qkv, const float2* __restrict__ tab,
                       __half* __restrict__ qh, __half* __restrict__ ql) {
    const float scale = 0.08838834764831845f;
    int t = blockIdx.x * blockDim.x + threadIdx.x;
    if (t >= Mrows * (NHq * Dh / 4)) return;
    int m = t / 1024;
    int cc = (t % 1024) * 4;
    int h = cc >> 7, d = cc & 127;
    int b = m >> 11, s = m & 2047;
    float4 v = *(const float4*)(qkv + (size_t)m * QKVW + cc);
    int p0 = d >> 1;
    float2 t0 = tab[s * 64 + p0];
    float2 t1 = tab[s * 64 + p0 + 1];
    float f[4];
    f[0] = (v.x * t0.x - v.y * t0.y) * scale;
    f[1] = (v.y * t0.x + v.x * t0.y) * scale;
    f[2] = (v.z * t1.x - v.w * t1.y) * scale;
    f[3] = (v.w * t1.x + v.z * t1.y) * scale;
    size_t o = ((size_t)((b * NHq + h) * Sq + s)) * Dh + d;
    __half hh[4], hl[4];
#pragma unroll
    for (int i = 0; i < 4; i++) {
        hh[i] = __float2half_rn(f[i]);
        hl[i] = __float2half_rn(f[i] - __half2float(hh[i]));
    }
    *(uint2*)(qh + o) = *(uint2*)hh;
    *(uint2*)(ql + o) = *(uint2*)hl;
}

// fused RoPE (table) + k split
__global__ void prep_k(const float* __restrict__ qkv, const float2* __restrict__ tab,
                       __half* __restrict__ kh, __half* __restrict__ kl) {
    int t = blockIdx.x * blockDim.x + threadIdx.x;
    if (t >= Mrows * (NKVq * Dh / 4)) return;
    int m = t / 256;
    int cc = (t % 256) * 4;
    int kvh = cc >> 7, d = cc & 127;
    int b = m >> 11, s = m & 2047;
    float4 v = *(const float4*)(qkv + (size_t)m * QKVW + NHq * Dh + cc);
    int p0 = d >> 1;
    float2 t0 = tab[s * 64 + p0];
    float2 t1 = tab[s * 64 + p0 + 1];
    float f[4];
    f[0] = v.x * t0.x - v.y * t0.y;
    f[1] = v.y * t0.x + v.x * t0.y;
    f[2] = v.z * t1.x - v.w * t1.y;
    f[3] = v.w * t1.x + v.z * t1.y;
    size_t o = ((size_t)((b * NKVq + kvh) * Sq + s)) * Dh + d;
    __half hh[4], hl[4];
#pragma unroll
    for (int i = 0; i < 4; i++) {
        hh[i] = __float2half_rn(f[i]);
        hl[i] = __float2half_rn(f[i] - __half2float(hh[i]));
    }
    *(uint2*)(kh + o) = *(uint2*)hh;
    *(uint2*)(kl + o) = *(uint2*)hl;
}

__global__ void prep_vt(const float* __restrict__ qkv, __half* __restrict__ vth) {
    __shared__ float t[32][33];
    int bk = blockIdx.z;
    int b = bk >> 3, kvh = bk & 7;
    int x = blockIdx.x * 32 + threadIdx.x;   // d
    int y0 = blockIdx.y * 32;                // s
    const float* src = qkv + (size_t)(b * Sq) * QKVW + (NHq + NKVq) * Dh + kvh * Dh;
#pragma unroll
    for (int j = threadIdx.y; j < 32; j += 8)
        t[j][threadIdx.x] = src[(size_t)(y0 + j) * QKVW + x];
    __syncthreads();
    int xo = y0 + threadIdx.x;      // s
    int yo0 = blockIdx.x * 32;      // d
#pragma unroll
    for (int j = threadIdx.y; j < 32; j += 8) {
        float v = t[threadIdx.x][j];
        int d = yo0 + j;
        vth[((size_t)bk * Dh + d) * Sq + xo] = __float2half_rn(v);
    }
}

// ===========================================================================
// Causal GQA flash attention (R16-proven): split-fp16 QK^T, single-fp16 PV,
// 2 CTAs/SM, split prefetch; epilogue emits frag-order A tiles for GEMM2.
// ===========================================================================
__global__ __launch_bounds__(256, 2) void attn_kernel(const __half* __restrict__ qh,
                                                      const __half* __restrict__ ql,
                                                      const __half* __restrict__ kh,
                                                      const __half* __restrict__ kl,
                                                      const __half* __restrict__ vth,
                                                      __half* __restrict__ att) {
    extern __shared__ char smc[];
    const uint32_t SMB = smem_u32(smc);
    float* Ss  = (float*)(smc + SM_SS);
    float* m_s = (float*)(smc + SM_MS);
    float* l_s = (float*)(smc + SM_LS);
    float* c_s = (float*)(smc + SM_CS);

    int tid  = threadIdx.x;
    int lane = tid & 31, wid = tid >> 5;
    int g = lane >> 2, q = lane & 3;
    int wm = wid & 1, wn = wid >> 1;

    int qtile = blockIdx.x;
    int bh    = blockIdx.y;
    int b     = bh >> 5;
    int h     = bh & 31;
    int kvh   = h >> 2;

    const __half* qhb = qh + ((size_t)((b * NHq + h) * Sq + qtile * 64)) * Dh;
    const __half* qlb = ql + ((size_t)((b * NHq + h) * Sq + qtile * 64)) * Dh;
    const __half* khb = kh + ((size_t)((b * NKVq + kvh) * Sq)) * Dh;
    const __half* klb = kl + ((size_t)((b * NKVq + kvh) * Sq)) * Dh;
    const __half* vthb = vth + ((size_t)(b * NKVq + kvh) * Dh) * Sq;

    int krow = tid >> 2, kc0 = (tid & 3) * 4;
    int vrow = tid >> 1, vc0 = (tid & 1) * 4;

    // --- prologue: load Q + K[0] + V[0]
    {
#pragma unroll
        for (int cc = 0; cc < 4; cc++) {
            int c = kc0 + cc;
            int kc = c >> 3;
            uint32_t so = (uint32_t)(((c & 7) ^ (krow & 7)) << 4);
            uint32_t dst = SMB + kc * 8192 + krow * 128 + so;
            CP16(dst + SM_QH, (const char*)(qhb + (size_t)krow * Dh + c * 8));
            CP16(dst + SM_QL, (const char*)(qlb + (size_t)krow * Dh + c * 8));
        }
        const __half* kph = khb + (size_t)krow * Dh;
        const __half* kpl = klb + (size_t)krow * Dh;
#pragma unroll
        for (int cc = 0; cc < 4; cc++) {
            int c = kc0 + cc;
            int kc = c >> 3;
            uint32_t so = (uint32_t)(((c & 7) ^ (krow & 7)) << 4);
            uint32_t dst = SMB + SM_KH + kc * 8192 + krow * 128 + so;
            CP16(dst, (const char*)(kph + c * 8));
            CP16(dst + 16384, (const char*)(kpl + c * 8));
        }
        const __half* vph = vthb + (size_t)vrow * Sq;
#pragma unroll
        for (int cc = 0; cc < 4; cc++) {
            int c = vc0 + cc;
            uint32_t so = (uint32_t)((c ^ (vrow & 7)) << 4);
            CP16(SMB + SM_VT + vrow * 128 + so, (const char*)(vph + c * 8));
        }
        CP_COMMIT();
    }
    if (tid < 64) { m_s[tid] = -1e30f; l_s[tid] = 0.0f; }

    int srow = tid >> 2, ssub = tid & 3;

    uint32_t qAoff[2], kBoff[2], pAoff[2], vBoff[4];
#pragma unroll
    for (int i = 0; i < 2; i++) {
        qAoff[i] = (uint32_t)((wm * 32 + i * 16 + g) * 128 + q * 4);
        pAoff[i] = qAoff[i];
    }
#pragma unroll
    for (int j = 0; j < 2; j++)
        kBoff[j] = (uint32_t)((wn * 16 + j * 8 + g) * 128 + q * 4);
#pragma unroll
    for (int j = 0; j < 4; j++)
        vBoff[j] = (uint32_t)((wn * 32 + j * 8 + g) * 128 + q * 4);

    float oacc[2][4][4] = {};

    for (int kt = 0; kt <= qtile; kt++) {
        CP_WAIT(0);
        __syncthreads();

        // --- QK^T: split fp16 MMA (Qh*Kh + Qh*Kl + Ql*Kh)
        float sacc[2][2][4] = {};
#pragma unroll
        for (int kc = 0; kc < 2; kc++) {
            uint32_t qbh = SMB + SM_QH + kc * 8192, qbl = SMB + SM_QL + kc * 8192;
            uint32_t kbh = SMB + SM_KH + kc * 8192, kbl = SMB + SM_KL + kc * 8192;
#pragma unroll
            for (int ks = 0; ks < 4; ks++) {
                uint32_t o0 = (uint32_t)(((2 * ks) ^ g) << 4);
                uint32_t o1 = (uint32_t)(((2 * ks + 1) ^ g) << 4);
                uint32_t aH[2][4], aL[2][4], bH[2][2], bL[2][2];
#pragma unroll
                for (int i = 0; i < 2; i++) {
                    uint32_t rh = qbh + qAoff[i], rl2 = qbl + qAoff[i];
                    aH[i][0] = lds32(rh + o0); aH[i][1] = lds32(rh + 1024 + o0);
                    aH[i][2] = lds32(rh + o1); aH[i][3] = lds32(rh + 1024 + o1);
                    aL[i][0] = lds32(rl2 + o0); aL[i][1] = lds32(rl2 + 1024 + o0);
                    aL[i][2] = lds32(rl2 + o1); aL[i][3] = lds32(rl2 + 1024 + o1);
                }
#pragma unroll
                for (int j = 0; j < 2; j++) {
                    uint32_t rh = kbh + kBoff[j], rl2 = kbl + kBoff[j];
                    bH[j][0] = lds32(rh + o0); bH[j][1] = lds32(rh + o1);
                    bL[j][0] = lds32(rl2 + o0); bL[j][1] = lds32(rl2 + o1);
                }
#pragma unroll
                for (int i = 0; i < 2; i++)
#pragma unroll
                    for (int j = 0; j < 2; j++) {
                        mma_f16(sacc[i][j], aH[i], bH[j]);
                        mma_f16(sacc[i][j], aH[i], bL[j]);
                        mma_f16(sacc[i][j], aL[i], bH[j]);
                    }
            }
        }
#pragma unroll
        for (int i = 0; i < 2; i++)
#pragma unroll
            for (int j = 0; j < 2; j++) {
                int r0 = wm * 32 + i * 16 + g;
                int cc = wn * 16 + j * 8 + 2 * q;
                *(float2*)&Ss[r0 * 66 + cc]       = make_float2(sacc[i][j][0], sacc[i][j][1]);
                *(float2*)&Ss[(r0 + 8) * 66 + cc] = make_float2(sacc[i][j][2], sacc[i][j][3]);
            }
        __syncthreads();

        // --- online softmax (4 threads/row), write P fp16
        {
            int limit = (kt == qtile) ? srow : 63;
            float tm = -1e30f;
            float pv_[16];
#pragma unroll
            for (int j = 0; j < 16; j++) {
                int c = ssub * 16 + j;
                float v = Ss[srow * 66 + c];
                if (c <= limit) tm = fmaxf(tm, v);
            }
            tm = fmaxf(tm, __shfl_xor_sync(0xFFFFFFFFu, tm, 1));
            tm = fmaxf(tm, __shfl_xor_sync(0xFFFFFFFFu, tm, 2));
            float mold = m_s[srow];
            float mnew = fmaxf(mold, tm);
            float sum = 0.0f;
#pragma unroll
            for (int j = 0; j < 16; j++) {
                int c = ssub * 16 + j;
                float p = (c <= limit) ? __expf(Ss[srow * 66 + c] - mnew) : 0.0f;
                pv_[j] = p;
                sum += p;
            }
#pragma unroll
            for (int c2 = 0; c2 < 2; c2++) {
                int c = ssub * 2 + c2;
                uint32_t hw[4];
#pragma unroll
                for (int t2 = 0; t2 < 4; t2++) {
                    __half2 hh = __floats2half2_rn(pv_[c2 * 8 + 2 * t2], pv_[c2 * 8 + 2 * t2 + 1]);
                    hw[t2] = *(uint32_t*)&hh;
                }
                uint32_t so = (uint32_t)((c ^ (srow & 7)) << 4);
                sts128(SMB + SM_PH + srow * 128 + so, make_uint4(hw[0], hw[1], hw[2], hw[3]));
            }
            sum += __shfl_xor_sync(0xFFFFFFFFu, sum, 1);
            sum += __shfl_xor_sync(0xFFFFFFFFu, sum, 2);
            if (ssub == 0) {
                float corr = __expf(mold - mnew);
                l_s[srow] = l_s[srow] * corr + sum;
                m_s[srow] = mnew;
                c_s[srow] = corr;
            }
        }
        __syncthreads();

        // K buffer dead: prefetch K[kt+1] under PV compute
        if (kt < qtile) {
            const __half* kph = khb + (size_t)((kt + 1) * 64 + krow) * Dh;
            const __half* kpl = klb + (size_t)((kt + 1) * 64 + krow) * Dh;
#pragma unroll
            for (int cc = 0; cc < 4; cc++) {
                int c = kc0 + cc;
                int kc = c >> 3;
                uint32_t so = (uint32_t)(((c & 7) ^ (krow & 7)) << 4);
                uint32_t dst = SMB + SM_KH + kc * 8192 + krow * 128 + so;
                CP16(dst, (const char*)(kph + c * 8));
                CP16(dst + 16384, (const char*)(kpl + c * 8));
            }
            CP_COMMIT();
        }

        // --- O rescale, then O += P @ VT (single fp16 MMA)
        float cr0[2], cr1[2];
#pragma unroll
        for (int i = 0; i < 2; i++) {
            cr0[i] = c_s[wm * 32 + i * 16 + g];
            cr1[i] = c_s[wm * 32 + i * 16 + 8 + g];
        }
#pragma unroll
        for (int i = 0; i < 2; i++)
#pragma unroll
            for (int j = 0; j < 4; j++) {
                oacc[i][j][0] *= cr0[i]; oacc[i][j][1] *= cr0[i];
                oacc[i][j][2] *= cr1[i]; oacc[i][j][3] *= cr1[i];
            }

#pragma unroll
        for (int ks = 0; ks < 4; ks++) {
            uint32_t o0 = (uint32_t)(((2 * ks) ^ g) << 4);
            uint32_t o1 = (uint32_t)(((2 * ks + 1) ^ g) << 4);
            uint32_t aH[2][4], bH[4][2];
#pragma unroll
            for (int i = 0; i < 2; i++) {
                uint32_t rh = SMB + SM_PH + pAoff[i];
                aH[i][0] = lds32(rh + o0); aH[i][1] = lds32(rh + 1024 + o0);
                aH[i][2] = lds32(rh + o1); aH[i][3] = lds32(rh + 1024 + o1);
            }
#pragma unroll
            for (int j = 0; j < 4; j++) {
                uint32_t rh = SMB + SM_VT + vBoff[j];
                bH[j][0] = lds32(rh + o0); bH[j][1] = lds32(rh + o1);
            }
#pragma unroll
            for (int i = 0; i < 2; i++)
#pragma unroll
                for (int j = 0; j < 4; j++)
                    mma_f16(oacc[i][j], aH[i], bH[j]);
        }
        __syncthreads();   // all VT reads done

        // V buffer dead: prefetch V[kt+1]
        if (kt < qtile) {
            const __half* vph = vthb + (size_t)vrow * Sq + (kt + 1) * 64;
#pragma unroll
            for (int cc = 0; cc < 4; cc++) {
                int c = vc0 + cc;
                uint32_t so = (uint32_t)((c ^ (vrow & 7)) << 4);
                CP16(SMB + SM_VT + vrow * 128 + so, (const char*)(vph + c * 8));
            }
            CP_COMMIT();
        }
    }

    // --- epilogue: O / l -> frag-order A tiles for GEMM2
    {
        int mtileA = (b * Sq + qtile * 64) >> 7;
        uint32_t wmHalf = (uint32_t)(qtile & 1) * 8192;
#pragma unroll
        for (int i = 0; i < 2; i++) {
            int ra = wm * 32 + i * 16 + g;
            float la = 1.0f / l_s[ra];
            float lb = 1.0f / l_s[ra + 8];
            uint32_t iblk = (uint32_t)(wm * 2 + i) * 512;
#pragma unroll
            for (int j = 0; j < 4; j++) {
                int kchunk = 2 * h + (wn >> 1);
                int ks = (wn & 1) * 2 + (j >> 1);
                __half2 va = __floats2half2_rn(oacc[i][j][0] * la, oacc[i][j][1] * la);
                __half2 vb = __floats2half2_rn(oacc[i][j][2] * lb, oacc[i][j][3] * lb);
                char* base = (char*)att + ((size_t)mtileA * NKCH + kchunk) * 16384
                             + wmHalf + ks * 2048 + iblk + (g * 4 + q) * 16 + (j & 1) * 8;
                *(uint2*)base = make_uint2(*(uint32_t*)&va, *(uint32_t*)&vb);
            }
        }
    }
}

// ===========================================================================
extern "C" void kernel_launch(void* const* d_in, const int* in_sizes, int n_in,
                              void* d_out, int out_size) {
    const float* hs   = (const float*)d_in[0];
    const float* wqkv = (const float*)d_in[2];
    const float* wo   = (const float*)d_in[3];
    float* out = (float*)d_out;

    float* qkvp;
    float2* ropep;
    __half *attp, *hsr, *wqkvT, *woT, *qhp, *qlp, *khp, *klp, *vthp;
    cudaGetSymbolAddress((void**)&qkvp, g_qkv);
    cudaGetSymbolAddress((void**)&ropep, g_rope);
    cudaGetSymbolAddress((void**)&attp, g_att);
    cudaGetSymbolAddress((void**)&hsr, g_hsr);
    cudaGetSymbolAddress((void**)&wqkvT, g_wqkvT);
    cudaGetSymbolAddress((void**)&woT, g_woT);
    cudaGetSymbolAddress((void**)&qhp, g_qh);
    cudaGetSymbolAddress((void**)&qlp, g_ql);
    cudaGetSymbolAddress((void**)&khp, g_kh);
    cudaGetSymbolAddress((void**)&klp, g_kl);
    cudaGetSymbolAddress((void**)&vthp, g_vth);

    const int GEMM_SMEM = NSTG * STAGE_BYTES;   // 96 KB
    cudaFuncSetAttribute((const void*)mma_gemm,
                         cudaFuncAttributeMaxDynamicSharedMemorySize, GEMM_SMEM);
    cudaFuncSetAttribute((const void*)attn_kernel,
                         cudaFuncAttributeMaxDynamicSharedMemorySize, ATTN_SMEM);

    // 0) operand prep: frag-order tiles + rope table
    rope_table<<<(Sq * 64 + 255) / 256, 256>>>(ropep);
    prep_a_frag<<<dim3(NKCH, Mrows / 128), 256>>>(hs, hsr);
    prep_b_frag<<<dim3(NKCH, QKVW / 128), 256>>>(wqkv, wqkvT, QKVW);
    prep_b_frag<<<dim3(NKCH, H_DIM / 128), 256>>>(wo, woT, H_DIM);

    // 1) QKV GEMM
    mma_gemm<<<dim3(QKVW / 128, Mrows / 128), 256, GEMM_SMEM>>>(hsr, wqkvT, qkvp, QKVW);

    // 2+3) fused RoPE(table) + split-fp16 operand prep
    prep_q<<<(Mrows * 1024 + 255) / 256, 256>>>(qkvp, ropep, qhp, qlp);
    prep_k<<<(Mrows * 256 + 255) / 256, 256>>>(qkvp, ropep, khp, klp);
    prep_vt<<<dim3(Dh / 32, Sq / 32, Bq * NKVq), dim3(32, 8)>>>(qkvp, vthp);

    // 4) attention
    attn_kernel<<<dim3(Sq / 64, Bq * NHq), 256, ATTN_SMEM>>>(qhp, qlp, khp, klp,
                                                             vthp, attp);

    // 5) output GEMM
    mma_gemm<<<dim3(H_DIM / 128, Mrows / 128), 256, GEMM_SMEM>>>(attp, woT, out, H_DIM);
}